// round 4
// baseline (speedup 1.0000x reference)
#include <cuda_runtime.h>

// Problem constants
#define Bn  4
#define Nn  2048
#define Dn  512
#define Hn  8
#define HDn 64
#define MT  (Bn*Nn)   // 8192 rows

// Scratch (allocation-free rule: __device__ globals)
__device__ float g_q[MT*Dn];
__device__ float g_k[MT*Dn];
__device__ float g_v[MT*Dn];
__device__ float g_attn[MT*Dn];

// ---------------------------------------------------------------------------
// GEMM: C[M,Nc] = A[M,K] @ W[Nc,K]^T   (torch Linear convention x @ W.T)
// 64x64 tile per CTA, BK=16, 256 threads, 4x4 register micro-tile.
// ---------------------------------------------------------------------------
__global__ __launch_bounds__(256) void gemm_nt(const float* __restrict__ A,
                                               const float* __restrict__ W,
                                               float* __restrict__ C,
                                               int M, int Nc, int K) {
    __shared__ float As[16][68];   // [k][m], pad 68 keeps float4 alignment
    __shared__ float Ws[16][68];   // [k][n]
    const int tid = threadIdx.x;
    const int tx = tid & 15, ty = tid >> 4;
    const int m0 = blockIdx.y * 64, n0 = blockIdx.x * 64;
    const int lrow = tid >> 2;           // 0..63
    const int lc4  = (tid & 3) * 4;      // 0,4,8,12

    float acc[4][4] = {};

    for (int kk = 0; kk < K; kk += 16) {
        float4 va = *reinterpret_cast<const float4*>(A + (size_t)(m0 + lrow) * K + kk + lc4);
        float4 vw = *reinterpret_cast<const float4*>(W + (size_t)(n0 + lrow) * K + kk + lc4);
        As[lc4+0][lrow] = va.x; As[lc4+1][lrow] = va.y;
        As[lc4+2][lrow] = va.z; As[lc4+3][lrow] = va.w;
        Ws[lc4+0][lrow] = vw.x; Ws[lc4+1][lrow] = vw.y;
        Ws[lc4+2][lrow] = vw.z; Ws[lc4+3][lrow] = vw.w;
        __syncthreads();

        #pragma unroll
        for (int k = 0; k < 16; k++) {
            float4 a = *reinterpret_cast<float4*>(&As[k][ty * 4]);
            float4 w = *reinterpret_cast<float4*>(&Ws[k][tx * 4]);
            float av[4] = {a.x, a.y, a.z, a.w};
            float wv[4] = {w.x, w.y, w.z, w.w};
            #pragma unroll
            for (int i = 0; i < 4; i++)
                #pragma unroll
                for (int j = 0; j < 4; j++)
                    acc[i][j] = fmaf(av[i], wv[j], acc[i][j]);
        }
        __syncthreads();
    }

    #pragma unroll
    for (int i = 0; i < 4; i++) {
        float4 o = {acc[i][0], acc[i][1], acc[i][2], acc[i][3]};
        *reinterpret_cast<float4*>(C + (size_t)(m0 + ty * 4 + i) * Nc + n0 + tx * 4) = o;
    }
}

// ---------------------------------------------------------------------------
// Flash attention per (b, h, 64-row q tile). Online softmax.
// scores = (Q Wq)(K Wk)^T / sqrt(HD) + bias;  masked keys -> -1e30.
// Q is pre-scaled by 1/8 at load. K tile stored transposed in smem so both
// operands of the S-compute inner loop are broadcast / LDS.128 conflict-free.
// Mask arrives as int32 (harness marshals bool -> int32).
// ---------------------------------------------------------------------------
#define PAD 68
#define ATTN_SMEM_BYTES (4*64*PAD*4 + 2*64*4)   // Qs,Kt,Vs,Ps + row_m,row_l = 70144

__global__ __launch_bounds__(256) void attn_kernel(const int* __restrict__ mask,
                                                   const float* __restrict__ bias) {
    extern __shared__ float sm[];
    float* Qs    = sm;                 // [64][PAD]  (q-row, dim), pre-scaled
    float* Kt    = Qs + 64 * PAD;      // [64][PAD]  (dim, key)   TRANSPOSED
    float* Vs    = Kt + 64 * PAD;      // [64][PAD]  (key, dim)
    float* Ps    = Vs + 64 * PAD;      // [64][PAD]  (q-row, key) probabilities
    float* row_m = Ps + 64 * PAD;      // [64]
    float* row_l = row_m + 64;         // [64]

    const int q0 = blockIdx.x * 64;
    const int h  = blockIdx.y;
    const int b  = blockIdx.z;
    const int tid = threadIdx.x;
    const int tx = tid & 15, ty = tid >> 4;   // 16x16 thread grid -> 4x4 micro-tile
    const int lrow = tid >> 2;                // loader mapping
    const int lc   = (tid & 3) * 16;

    // Load Q tile (scaled by 1/sqrt(HD) = 1/8)
    {
        const float* qg = g_q + ((size_t)(b * Nn) + q0 + lrow) * Dn + h * HDn + lc;
        #pragma unroll
        for (int i = 0; i < 4; i++) {
            float4 v = *reinterpret_cast<const float4*>(qg + i * 4);
            float4 s = {v.x * 0.125f, v.y * 0.125f, v.z * 0.125f, v.w * 0.125f};
            *reinterpret_cast<float4*>(&Qs[lrow * PAD + lc + i * 4]) = s;
        }
    }
    if (tid < 64) { row_m[tid] = -3e38f; row_l[tid] = 0.0f; }

    float o[4][4] = {};
    const int*   mb    = mask + (size_t)b * Nn;
    const float* biasb = bias + ((size_t)b * Nn + q0) * Nn;

    for (int kt = 0; kt < Nn / 64; kt++) {
        __syncthreads();   // previous PV done before overwriting Kt/Vs/Ps

        // Load K (transposed) and V tiles
        {
            const size_t base = ((size_t)(b * Nn) + (size_t)kt * 64 + lrow) * Dn + h * HDn + lc;
            const float* kg = g_k + base;
            const float* vg = g_v + base;
            #pragma unroll
            for (int i = 0; i < 4; i++) {
                float4 kv = *reinterpret_cast<const float4*>(kg + i * 4);
                Kt[(lc + i * 4 + 0) * PAD + lrow] = kv.x;
                Kt[(lc + i * 4 + 1) * PAD + lrow] = kv.y;
                Kt[(lc + i * 4 + 2) * PAD + lrow] = kv.z;
                Kt[(lc + i * 4 + 3) * PAD + lrow] = kv.w;
                float4 vv = *reinterpret_cast<const float4*>(vg + i * 4);
                *reinterpret_cast<float4*>(&Vs[lrow * PAD + lc + i * 4]) = vv;
            }
        }
        __syncthreads();

        // S = Qs @ Kt  (4x4 register tile per thread)
        float s[4][4] = {};
        #pragma unroll 8
        for (int k = 0; k < 64; k++) {
            float a0 = Qs[(ty * 4 + 0) * PAD + k];
            float a1 = Qs[(ty * 4 + 1) * PAD + k];
            float a2 = Qs[(ty * 4 + 2) * PAD + k];
            float a3 = Qs[(ty * 4 + 3) * PAD + k];
            float4 w = *reinterpret_cast<float4*>(&Kt[k * PAD + tx * 4]);
            s[0][0] = fmaf(a0, w.x, s[0][0]); s[0][1] = fmaf(a0, w.y, s[0][1]);
            s[0][2] = fmaf(a0, w.z, s[0][2]); s[0][3] = fmaf(a0, w.w, s[0][3]);
            s[1][0] = fmaf(a1, w.x, s[1][0]); s[1][1] = fmaf(a1, w.y, s[1][1]);
            s[1][2] = fmaf(a1, w.z, s[1][2]); s[1][3] = fmaf(a1, w.w, s[1][3]);
            s[2][0] = fmaf(a2, w.x, s[2][0]); s[2][1] = fmaf(a2, w.y, s[2][1]);
            s[2][2] = fmaf(a2, w.z, s[2][2]); s[2][3] = fmaf(a2, w.w, s[2][3]);
            s[3][0] = fmaf(a3, w.x, s[3][0]); s[3][1] = fmaf(a3, w.y, s[3][1]);
            s[3][2] = fmaf(a3, w.z, s[3][2]); s[3][3] = fmaf(a3, w.w, s[3][3]);
        }

        // + bias, apply key mask (int32 flags)
        const int kbase = kt * 64 + tx * 4;
        const int mk0 = mb[kbase + 0], mk1 = mb[kbase + 1];
        const int mk2 = mb[kbase + 2], mk3 = mb[kbase + 3];
        #pragma unroll
        for (int i = 0; i < 4; i++) {
            float4 bv = *reinterpret_cast<const float4*>(biasb + (size_t)(ty * 4 + i) * Nn + kbase);
            s[i][0] += bv.x; s[i][1] += bv.y; s[i][2] += bv.z; s[i][3] += bv.w;
            if (mk0) s[i][0] = -1e30f;
            if (mk1) s[i][1] = -1e30f;
            if (mk2) s[i][2] = -1e30f;
            if (mk3) s[i][3] = -1e30f;
        }

        // Online softmax (row groups of 16 lanes: same ty, tx = 0..15)
        #pragma unroll
        for (int i = 0; i < 4; i++) {
            float tmax = fmaxf(fmaxf(s[i][0], s[i][1]), fmaxf(s[i][2], s[i][3]));
            #pragma unroll
            for (int off = 1; off < 16; off <<= 1)
                tmax = fmaxf(tmax, __shfl_xor_sync(0xffffffffu, tmax, off));
            float mo = row_m[ty * 4 + i];
            float mn = fmaxf(mo, tmax);
            float sc = expf(mo - mn);
            float p0 = expf(s[i][0] - mn);
            float p1 = expf(s[i][1] - mn);
            float p2 = expf(s[i][2] - mn);
            float p3 = expf(s[i][3] - mn);
            float ps = p0 + p1 + p2 + p3;
            #pragma unroll
            for (int off = 1; off < 16; off <<= 1)
                ps += __shfl_xor_sync(0xffffffffu, ps, off);
            o[i][0] *= sc; o[i][1] *= sc; o[i][2] *= sc; o[i][3] *= sc;
            float ln = row_l[ty * 4 + i] * sc + ps;
            float4 pv = {p0, p1, p2, p3};
            *reinterpret_cast<float4*>(&Ps[(ty * 4 + i) * PAD + tx * 4]) = pv;
            __syncwarp();
            if (tx == 0) { row_m[ty * 4 + i] = mn; row_l[ty * 4 + i] = ln; }
            __syncwarp();
        }
        __syncthreads();

        // O += P @ V
        #pragma unroll 8
        for (int c = 0; c < 64; c++) {
            float4 v = *reinterpret_cast<float4*>(&Vs[c * PAD + tx * 4]);
            float p0 = Ps[(ty * 4 + 0) * PAD + c];
            float p1 = Ps[(ty * 4 + 1) * PAD + c];
            float p2 = Ps[(ty * 4 + 2) * PAD + c];
            float p3 = Ps[(ty * 4 + 3) * PAD + c];
            o[0][0] = fmaf(p0, v.x, o[0][0]); o[0][1] = fmaf(p0, v.y, o[0][1]);
            o[0][2] = fmaf(p0, v.z, o[0][2]); o[0][3] = fmaf(p0, v.w, o[0][3]);
            o[1][0] = fmaf(p1, v.x, o[1][0]); o[1][1] = fmaf(p1, v.y, o[1][1]);
            o[1][2] = fmaf(p1, v.z, o[1][2]); o[1][3] = fmaf(p1, v.w, o[1][3]);
            o[2][0] = fmaf(p2, v.x, o[2][0]); o[2][1] = fmaf(p2, v.y, o[2][1]);
            o[2][2] = fmaf(p2, v.z, o[2][2]); o[2][3] = fmaf(p2, v.w, o[2][3]);
            o[3][0] = fmaf(p3, v.x, o[3][0]); o[3][1] = fmaf(p3, v.y, o[3][1]);
            o[3][2] = fmaf(p3, v.z, o[3][2]); o[3][3] = fmaf(p3, v.w, o[3][3]);
        }
    }

    // Normalize + write out [B,N,D] with head h at columns h*HD..
    #pragma unroll
    for (int i = 0; i < 4; i++) {
        float inv = 1.0f / row_l[ty * 4 + i];
        float4 ov = {o[i][0] * inv, o[i][1] * inv, o[i][2] * inv, o[i][3] * inv};
        *reinterpret_cast<float4*>(
            &g_attn[((size_t)(b * Nn) + q0 + ty * 4 + i) * Dn + h * HDn + tx * 4]) = ov;
    }
}

// ---------------------------------------------------------------------------
// Launch: 3 projection GEMMs -> flash attention -> output GEMM
// Inputs (metadata order): q, mask, attn_bias, Wq, Wk, Wv, Wo
// ---------------------------------------------------------------------------
extern "C" void kernel_launch(void* const* d_in, const int* in_sizes, int n_in,
                              void* d_out, int out_size) {
    const float* q    = (const float*)d_in[0];
    const int*   mask = (const int*)d_in[1];
    const float* bias = (const float*)d_in[2];
    const float* Wq   = (const float*)d_in[3];
    const float* Wk   = (const float*)d_in[4];
    const float* Wv   = (const float*)d_in[5];
    const float* Wo   = (const float*)d_in[6];
    float* out = (float*)d_out;

    float *gq, *gk, *gv, *ga;
    cudaGetSymbolAddress((void**)&gq, g_q);
    cudaGetSymbolAddress((void**)&gk, g_k);
    cudaGetSymbolAddress((void**)&gv, g_v);
    cudaGetSymbolAddress((void**)&ga, g_attn);

    dim3 gemm_grid(Dn / 64, MT / 64);   // (8, 128)
    gemm_nt<<<gemm_grid, 256>>>(q, Wq, gq, MT, Dn, Dn);
    gemm_nt<<<gemm_grid, 256>>>(q, Wk, gk, MT, Dn, Dn);
    gemm_nt<<<gemm_grid, 256>>>(q, Wv, gv, MT, Dn, Dn);

    cudaFuncSetAttribute(attn_kernel, cudaFuncAttributeMaxDynamicSharedMemorySize,
                         ATTN_SMEM_BYTES);
    attn_kernel<<<dim3(Nn / 64, Hn, Bn), 256, ATTN_SMEM_BYTES>>>(mask, bias);

    gemm_nt<<<gemm_grid, 256>>>(ga, Wo, out, MT, Dn, Dn);
}

// round 6
// speedup vs baseline: 1.2177x; 1.2177x over previous
#include <cuda_runtime.h>
#include <cuda_bf16.h>
#include <cstdint>

// Problem constants
#define Bn  4
#define Nn  2048
#define Dn  512
#define Hn  8
#define HDn 64
#define MT  (Bn*Nn)   // 8192 rows

// Scratch (allocation-free rule: __device__ globals)
__device__ float g_q[MT*Dn];
__device__ float g_k[MT*Dn];
__device__ float g_v[MT*Dn];
__device__ float g_attn[MT*Dn];

// ===========================================================================
// bf16x3 tensor-core GEMM via mma.sync (arch-neutral PTX, lowers to HMMA)
//   C[M,512] = A[M,512] @ W[512,512]^T
// CTA: 256 threads (8 warps), tile 128x128, BK=32, 2-stage smem pipeline.
// Each fp32 split into bf16 hi + bf16 residual; D += Ah*Bh + Ah*Bl + Al*Bh.
// ===========================================================================
#define BK    32
#define SAstr 36                    // bf16 elems per smem row (bank-conflict-free)
#define ARR_B (128*SAstr*2)         // 9216 B per array
#define STG_B (4*ARR_B)             // A_hi | A_lo | W_hi | W_lo
#define SMEM_GEMM (2*STG_B)         // 73728 B

__device__ __forceinline__ void mma_bf16(float* c, const uint32_t* a, const uint32_t* b) {
    asm volatile("mma.sync.aligned.m16n8k16.row.col.f32.bf16.bf16.f32 "
        "{%0,%1,%2,%3}, {%4,%5,%6,%7}, {%8,%9}, {%0,%1,%2,%3};"
        : "+f"(c[0]), "+f"(c[1]), "+f"(c[2]), "+f"(c[3])
        : "r"(a[0]), "r"(a[1]), "r"(a[2]), "r"(a[3]), "r"(b[0]), "r"(b[1]));
}

__device__ __forceinline__ uint32_t packbf_hi(float x, float y, float& rx, float& ry) {
    __nv_bfloat16 hx = __float2bfloat16(x), hy = __float2bfloat16(y);
    rx = x - __bfloat162float(hx);
    ry = y - __bfloat162float(hy);
    return (uint32_t)__bfloat16_as_ushort(hx) | ((uint32_t)__bfloat16_as_ushort(hy) << 16);
}
__device__ __forceinline__ uint32_t packbf(float x, float y) {
    return (uint32_t)__bfloat16_as_ushort(__float2bfloat16(x)) |
           ((uint32_t)__bfloat16_as_ushort(__float2bfloat16(y)) << 16);
}

__global__ __launch_bounds__(256) void gemm_bf16x3(
    const float* __restrict__ A,
    const float* __restrict__ W0, const float* __restrict__ W1, const float* __restrict__ W2,
    float* __restrict__ C0, float* __restrict__ C1, float* __restrict__ C2)
{
    extern __shared__ __align__(16) char smg[];
    const int tid  = threadIdx.x;
    const int lane = tid & 31;
    const int wid  = tid >> 5;
    const int g    = lane >> 2;        // groupID
    const int tg   = lane & 3;         // thread-in-group
    const int n0 = blockIdx.x * 128, m0 = blockIdx.y * 128;
    const float* W = (blockIdx.z == 0) ? W0 : (blockIdx.z == 1 ? W1 : W2);
    float*       C = (blockIdx.z == 0) ? C0 : (blockIdx.z == 1 ? C1 : C2);
    const int wm = (wid & 3) * 32;     // warp m-offset (4 warps along M)
    const int wn = (wid >> 2) * 64;    // warp n-offset (2 warps along N)

    const float* Ab = A + (size_t)m0 * Dn;
    const float* Wb = W + (size_t)n0 * Dn;

    // 256 threads load a 128x32 fp32 tile of A and of W per chunk (4 float4 each)
    auto prefetch = [&](int kc, float4* pa, float4* pw) {
        #pragma unroll
        for (int t = 0; t < 4; t++) {
            int id = tid + t * 256;
            int row = id >> 3, c4 = id & 7;
            pa[t] = *reinterpret_cast<const float4*>(Ab + (size_t)row * Dn + kc * BK + c4 * 4);
            pw[t] = *reinterpret_cast<const float4*>(Wb + (size_t)row * Dn + kc * BK + c4 * 4);
        }
    };
    auto stage_store = [&](int st, const float4* pa, const float4* pw) {
        char* s = smg + st * STG_B;
        #pragma unroll
        for (int t = 0; t < 4; t++) {
            int id = tid + t * 256;
            int row = id >> 3, c4 = id & 7;
            size_t off = ((size_t)row * SAstr + c4 * 4) * 2;
            float r0, r1, r2, r3;
            uint32_t h01 = packbf_hi(pa[t].x, pa[t].y, r0, r1);
            uint32_t h23 = packbf_hi(pa[t].z, pa[t].w, r2, r3);
            *reinterpret_cast<uint2*>(s + off)                 = make_uint2(h01, h23);
            *reinterpret_cast<uint2*>(s + ARR_B + off)         = make_uint2(packbf(r0, r1), packbf(r2, r3));
            uint32_t w01 = packbf_hi(pw[t].x, pw[t].y, r0, r1);
            uint32_t w23 = packbf_hi(pw[t].z, pw[t].w, r2, r3);
            *reinterpret_cast<uint2*>(s + 2 * ARR_B + off)     = make_uint2(w01, w23);
            *reinterpret_cast<uint2*>(s + 3 * ARR_B + off)     = make_uint2(packbf(r0, r1), packbf(r2, r3));
        }
    };

    float acc[2][8][4];
    #pragma unroll
    for (int t = 0; t < 2; t++)
        #pragma unroll
        for (int j = 0; j < 8; j++)
            #pragma unroll
            for (int e = 0; e < 4; e++) acc[t][j][e] = 0.0f;

    {
        float4 pa[4], pw[4];
        prefetch(0, pa, pw);
        stage_store(0, pa, pw);
    }
    __syncthreads();

    #pragma unroll 1
    for (int kc = 0; kc < Dn / BK; kc++) {
        float4 pa[4], pw[4];
        if (kc + 1 < Dn / BK) prefetch(kc + 1, pa, pw);

        const char* s = smg + (kc & 1) * STG_B;
        #pragma unroll
        for (int ks = 0; ks < 2; ks++) {
            const int k0 = ks * 16;
            // A fragments (hi/lo) for 2 m16-tiles
            uint32_t ah[2][4], al[2][4];
            #pragma unroll
            for (int t = 0; t < 2; t++) {
                int r = wm + t * 16 + g;
                size_t o0 = ((size_t)r * SAstr + k0 + tg * 2) * 2;
                size_t o1 = ((size_t)(r + 8) * SAstr + k0 + tg * 2) * 2;
                ah[t][0] = *reinterpret_cast<const uint32_t*>(s + o0);
                ah[t][1] = *reinterpret_cast<const uint32_t*>(s + o1);
                ah[t][2] = *reinterpret_cast<const uint32_t*>(s + o0 + 16);
                ah[t][3] = *reinterpret_cast<const uint32_t*>(s + o1 + 16);
                al[t][0] = *reinterpret_cast<const uint32_t*>(s + ARR_B + o0);
                al[t][1] = *reinterpret_cast<const uint32_t*>(s + ARR_B + o1);
                al[t][2] = *reinterpret_cast<const uint32_t*>(s + ARR_B + o0 + 16);
                al[t][3] = *reinterpret_cast<const uint32_t*>(s + ARR_B + o1 + 16);
            }
            // B fragments (hi/lo) for 8 n8-tiles (W is [n][k], k contiguous = col-major B)
            uint32_t bh[8][2], bl[8][2];
            #pragma unroll
            for (int j = 0; j < 8; j++) {
                int r = wn + j * 8 + g;
                size_t o = ((size_t)r * SAstr + k0 + tg * 2) * 2;
                bh[j][0] = *reinterpret_cast<const uint32_t*>(s + 2 * ARR_B + o);
                bh[j][1] = *reinterpret_cast<const uint32_t*>(s + 2 * ARR_B + o + 16);
                bl[j][0] = *reinterpret_cast<const uint32_t*>(s + 3 * ARR_B + o);
                bl[j][1] = *reinterpret_cast<const uint32_t*>(s + 3 * ARR_B + o + 16);
            }
            #pragma unroll
            for (int t = 0; t < 2; t++)
                #pragma unroll
                for (int j = 0; j < 8; j++) {
                    mma_bf16(acc[t][j], ah[t], bh[j]);
                    mma_bf16(acc[t][j], ah[t], bl[j]);
                    mma_bf16(acc[t][j], al[t], bh[j]);
                }
        }
        if (kc + 1 < Dn / BK) stage_store((kc + 1) & 1, pa, pw);
        __syncthreads();
    }

    // Epilogue: C fragment (c0,c1)=(row g, col 2tg..+1), (c2,c3)=row g+8
    #pragma unroll
    for (int t = 0; t < 2; t++)
        #pragma unroll
        for (int j = 0; j < 8; j++) {
            int row = m0 + wm + t * 16 + g;
            int col = n0 + wn + j * 8 + tg * 2;
            *reinterpret_cast<float2*>(C + (size_t)row * Dn + col) =
                make_float2(acc[t][j][0], acc[t][j][1]);
            *reinterpret_cast<float2*>(C + (size_t)(row + 8) * Dn + col) =
                make_float2(acc[t][j][2], acc[t][j][3]);
        }
}

// ---------------------------------------------------------------------------
// Flash attention per (b, h, 64-row q tile). Online softmax. (fp32, unchanged)
// ---------------------------------------------------------------------------
#define PAD 68
#define ATTN_SMEM_BYTES (4*64*PAD*4 + 2*64*4)

__global__ __launch_bounds__(256) void attn_kernel(const int* __restrict__ mask,
                                                   const float* __restrict__ bias) {
    extern __shared__ float sm[];
    float* Qs    = sm;
    float* Kt    = Qs + 64 * PAD;
    float* Vs    = Kt + 64 * PAD;
    float* Ps    = Vs + 64 * PAD;
    float* row_m = Ps + 64 * PAD;
    float* row_l = row_m + 64;

    const int q0 = blockIdx.x * 64;
    const int h  = blockIdx.y;
    const int b  = blockIdx.z;
    const int tid = threadIdx.x;
    const int tx = tid & 15, ty = tid >> 4;
    const int lrow = tid >> 2;
    const int lc   = (tid & 3) * 16;

    {
        const float* qg = g_q + ((size_t)(b * Nn) + q0 + lrow) * Dn + h * HDn + lc;
        #pragma unroll
        for (int i = 0; i < 4; i++) {
            float4 v = *reinterpret_cast<const float4*>(qg + i * 4);
            float4 s = {v.x * 0.125f, v.y * 0.125f, v.z * 0.125f, v.w * 0.125f};
            *reinterpret_cast<float4*>(&Qs[lrow * PAD + lc + i * 4]) = s;
        }
    }
    if (tid < 64) { row_m[tid] = -3e38f; row_l[tid] = 0.0f; }

    float o[4][4] = {};
    const int*   mb    = mask + (size_t)b * Nn;
    const float* biasb = bias + ((size_t)b * Nn + q0) * Nn;

    for (int kt = 0; kt < Nn / 64; kt++) {
        __syncthreads();
        {
            const size_t base = ((size_t)(b * Nn) + (size_t)kt * 64 + lrow) * Dn + h * HDn + lc;
            const float* kg = g_k + base;
            const float* vg = g_v + base;
            #pragma unroll
            for (int i = 0; i < 4; i++) {
                float4 kv = *reinterpret_cast<const float4*>(kg + i * 4);
                Kt[(lc + i * 4 + 0) * PAD + lrow] = kv.x;
                Kt[(lc + i * 4 + 1) * PAD + lrow] = kv.y;
                Kt[(lc + i * 4 + 2) * PAD + lrow] = kv.z;
                Kt[(lc + i * 4 + 3) * PAD + lrow] = kv.w;
                float4 vv = *reinterpret_cast<const float4*>(vg + i * 4);
                *reinterpret_cast<float4*>(&Vs[lrow * PAD + lc + i * 4]) = vv;
            }
        }
        __syncthreads();

        float s[4][4] = {};
        #pragma unroll 8
        for (int k = 0; k < 64; k++) {
            float a0 = Qs[(ty * 4 + 0) * PAD + k];
            float a1 = Qs[(ty * 4 + 1) * PAD + k];
            float a2 = Qs[(ty * 4 + 2) * PAD + k];
            float a3 = Qs[(ty * 4 + 3) * PAD + k];
            float4 w = *reinterpret_cast<float4*>(&Kt[k * PAD + tx * 4]);
            s[0][0] = fmaf(a0, w.x, s[0][0]); s[0][1] = fmaf(a0, w.y, s[0][1]);
            s[0][2] = fmaf(a0, w.z, s[0][2]); s[0][3] = fmaf(a0, w.w, s[0][3]);
            s[1][0] = fmaf(a1, w.x, s[1][0]); s[1][1] = fmaf(a1, w.y, s[1][1]);
            s[1][2] = fmaf(a1, w.z, s[1][2]); s[1][3] = fmaf(a1, w.w, s[1][3]);
            s[2][0] = fmaf(a2, w.x, s[2][0]); s[2][1] = fmaf(a2, w.y, s[2][1]);
            s[2][2] = fmaf(a2, w.z, s[2][2]); s[2][3] = fmaf(a2, w.w, s[2][3]);
            s[3][0] = fmaf(a3, w.x, s[3][0]); s[3][1] = fmaf(a3, w.y, s[3][1]);
            s[3][2] = fmaf(a3, w.z, s[3][2]); s[3][3] = fmaf(a3, w.w, s[3][3]);
        }

        const int kbase = kt * 64 + tx * 4;
        const int mk0 = mb[kbase + 0], mk1 = mb[kbase + 1];
        const int mk2 = mb[kbase + 2], mk3 = mb[kbase + 3];
        #pragma unroll
        for (int i = 0; i < 4; i++) {
            float4 bv = *reinterpret_cast<const float4*>(biasb + (size_t)(ty * 4 + i) * Nn + kbase);
            s[i][0] += bv.x; s[i][1] += bv.y; s[i][2] += bv.z; s[i][3] += bv.w;
            if (mk0) s[i][0] = -1e30f;
            if (mk1) s[i][1] = -1e30f;
            if (mk2) s[i][2] = -1e30f;
            if (mk3) s[i][3] = -1e30f;
        }

        #pragma unroll
        for (int i = 0; i < 4; i++) {
            float tmax = fmaxf(fmaxf(s[i][0], s[i][1]), fmaxf(s[i][2], s[i][3]));
            #pragma unroll
            for (int off = 1; off < 16; off <<= 1)
                tmax = fmaxf(tmax, __shfl_xor_sync(0xffffffffu, tmax, off));
            float mo = row_m[ty * 4 + i];
            float mn = fmaxf(mo, tmax);
            float sc = expf(mo - mn);
            float p0 = expf(s[i][0] - mn);
            float p1 = expf(s[i][1] - mn);
            float p2 = expf(s[i][2] - mn);
            float p3 = expf(s[i][3] - mn);
            float ps = p0 + p1 + p2 + p3;
            #pragma unroll
            for (int off = 1; off < 16; off <<= 1)
                ps += __shfl_xor_sync(0xffffffffu, ps, off);
            o[i][0] *= sc; o[i][1] *= sc; o[i][2] *= sc; o[i][3] *= sc;
            float ln = row_l[ty * 4 + i] * sc + ps;
            float4 pv = {p0, p1, p2, p3};
            *reinterpret_cast<float4*>(&Ps[(ty * 4 + i) * PAD + tx * 4]) = pv;
            __syncwarp();
            if (tx == 0) { row_m[ty * 4 + i] = mn; row_l[ty * 4 + i] = ln; }
            __syncwarp();
        }
        __syncthreads();

        #pragma unroll 8
        for (int c = 0; c < 64; c++) {
            float4 v = *reinterpret_cast<float4*>(&Vs[c * PAD + tx * 4]);
            float p0 = Ps[(ty * 4 + 0) * PAD + c];
            float p1 = Ps[(ty * 4 + 1) * PAD + c];
            float p2 = Ps[(ty * 4 + 2) * PAD + c];
            float p3 = Ps[(ty * 4 + 3) * PAD + c];
            o[0][0] = fmaf(p0, v.x, o[0][0]); o[0][1] = fmaf(p0, v.y, o[0][1]);
            o[0][2] = fmaf(p0, v.z, o[0][2]); o[0][3] = fmaf(p0, v.w, o[0][3]);
            o[1][0] = fmaf(p1, v.x, o[1][0]); o[1][1] = fmaf(p1, v.y, o[1][1]);
            o[1][2] = fmaf(p1, v.z, o[1][2]); o[1][3] = fmaf(p1, v.w, o[1][3]);
            o[2][0] = fmaf(p2, v.x, o[2][0]); o[2][1] = fmaf(p2, v.y, o[2][1]);
            o[2][2] = fmaf(p2, v.z, o[2][2]); o[2][3] = fmaf(p2, v.w, o[2][3]);
            o[3][0] = fmaf(p3, v.x, o[3][0]); o[3][1] = fmaf(p3, v.y, o[3][1]);
            o[3][2] = fmaf(p3, v.z, o[3][2]); o[3][3] = fmaf(p3, v.w, o[3][3]);
        }
    }

    #pragma unroll
    for (int i = 0; i < 4; i++) {
        float inv = 1.0f / row_l[ty * 4 + i];
        float4 ov = {o[i][0] * inv, o[i][1] * inv, o[i][2] * inv, o[i][3] * inv};
        *reinterpret_cast<float4*>(
            &g_attn[((size_t)(b * Nn) + q0 + ty * 4 + i) * Dn + h * HDn + tx * 4]) = ov;
    }
}

// ---------------------------------------------------------------------------
// Launch: fused QKV bf16x3 GEMM -> flash attention -> output bf16x3 GEMM
// Inputs (metadata order): q, mask, attn_bias, Wq, Wk, Wv, Wo
// ---------------------------------------------------------------------------
extern "C" void kernel_launch(void* const* d_in, const int* in_sizes, int n_in,
                              void* d_out, int out_size) {
    const float* q    = (const float*)d_in[0];
    const int*   mask = (const int*)d_in[1];
    const float* bias = (const float*)d_in[2];
    const float* Wq   = (const float*)d_in[3];
    const float* Wk   = (const float*)d_in[4];
    const float* Wv   = (const float*)d_in[5];
    const float* Wo   = (const float*)d_in[6];
    float* out = (float*)d_out;

    float *gq, *gk, *gv, *ga;
    cudaGetSymbolAddress((void**)&gq, g_q);
    cudaGetSymbolAddress((void**)&gk, g_k);
    cudaGetSymbolAddress((void**)&gv, g_v);
    cudaGetSymbolAddress((void**)&ga, g_attn);

    cudaFuncSetAttribute(gemm_bf16x3, cudaFuncAttributeMaxDynamicSharedMemorySize, SMEM_GEMM);
    cudaFuncSetAttribute(attn_kernel, cudaFuncAttributeMaxDynamicSharedMemorySize,
                         ATTN_SMEM_BYTES);

    // QKV projections fused into one launch (z selects weight/output)
    gemm_bf16x3<<<dim3(Dn / 128, MT / 128, 3), 256, SMEM_GEMM>>>(q, Wq, Wk, Wv, gq, gk, gv);

    attn_kernel<<<dim3(Nn / 64, Hn, Bn), 256, ATTN_SMEM_BYTES>>>(mask, bias);

    // Output projection
    gemm_bf16x3<<<dim3(Dn / 128, MT / 128, 1), 256, SMEM_GEMM>>>(ga, Wo, Wo, Wo, out, out, out);
}

// round 7
// speedup vs baseline: 2.2464x; 1.8448x over previous
#include <cuda_runtime.h>
#include <cuda_bf16.h>
#include <cstdint>

// Problem constants
#define Bn  4
#define Nn  2048
#define Dn  512
#define Hn  8
#define HDn 64
#define MT  (Bn*Nn)   // 8192 rows

// Scratch (allocation-free rule: __device__ globals)
__device__ __nv_bfloat16 g_qh[MT*Dn], g_ql[MT*Dn];           // Q proj, scaled 1/8, hi/lo
__device__ __nv_bfloat16 g_kh[MT*Dn], g_kl[MT*Dn];           // K proj [tok][dim]
__device__ __nv_bfloat16 g_vth[MT*Dn], g_vtl[MT*Dn];         // V proj transposed [(b,h,d)][tok]
__device__ float g_attn[MT*Dn];
__device__ float g_maskf[Bn*Nn];

// ===========================================================================
// common helpers
// ===========================================================================
__device__ __forceinline__ uint32_t smem_u32(const void* p) {
    uint32_t a;
    asm("{ .reg .u64 t; cvta.to.shared.u64 t, %1; cvt.u32.u64 %0, t; }" : "=r"(a) : "l"(p));
    return a;
}
__device__ __forceinline__ void mma_bf16(float* c, const uint32_t* a, const uint32_t* b) {
    asm volatile("mma.sync.aligned.m16n8k16.row.col.f32.bf16.bf16.f32 "
        "{%0,%1,%2,%3}, {%4,%5,%6,%7}, {%8,%9}, {%0,%1,%2,%3};"
        : "+f"(c[0]), "+f"(c[1]), "+f"(c[2]), "+f"(c[3])
        : "r"(a[0]), "r"(a[1]), "r"(a[2]), "r"(a[3]), "r"(b[0]), "r"(b[1]));
}
__device__ __forceinline__ void ldm_x4(uint32_t* r, uint32_t saddr) {
    asm volatile("ldmatrix.sync.aligned.m8n8.x4.shared.b16 {%0,%1,%2,%3}, [%4];"
        : "=r"(r[0]), "=r"(r[1]), "=r"(r[2]), "=r"(r[3]) : "r"(saddr));
}
__device__ __forceinline__ void cp16(uint32_t saddr, const void* g) {
    asm volatile("cp.async.ca.shared.global [%0], [%1], 16;" :: "r"(saddr), "l"(g));
}
__device__ __forceinline__ void cp_commit() { asm volatile("cp.async.commit_group;" ::: "memory"); }
__device__ __forceinline__ void cp_wait0()  { asm volatile("cp.async.wait_group 0;" ::: "memory"); }

__device__ __forceinline__ uint32_t packbf_hi(float x, float y, float& rx, float& ry) {
    __nv_bfloat16 hx = __float2bfloat16(x), hy = __float2bfloat16(y);
    rx = x - __bfloat162float(hx);
    ry = y - __bfloat162float(hy);
    return (uint32_t)__bfloat16_as_ushort(hx) | ((uint32_t)__bfloat16_as_ushort(hy) << 16);
}
__device__ __forceinline__ uint32_t packbf(float x, float y) {
    return (uint32_t)__bfloat16_as_ushort(__float2bfloat16(x)) |
           ((uint32_t)__bfloat16_as_ushort(__float2bfloat16(y)) << 16);
}
__device__ __forceinline__ void packhl(float x, float y, uint32_t& h, uint32_t& l) {
    float rx, ry;
    h = packbf_hi(x, y, rx, ry);
    l = packbf(rx, ry);
}

// ===========================================================================
// mask -> float addend (0 / -1e30)
// ===========================================================================
__global__ void mask_prep(const int* __restrict__ mask) {
    int i = blockIdx.x * blockDim.x + threadIdx.x;
    if (i < Bn * Nn) g_maskf[i] = mask[i] ? -1e30f : 0.0f;
}

// ===========================================================================
// bf16x3 GEMM mainloop (shared by both GEMM kernels)
// CTA 256 thr, tile 128x128, BK=32, 2-stage smem, 4x2 warp grid (m x n)
// ===========================================================================
#define BK    32
#define SAstr 36
#define ARR_B (128*SAstr*2)
#define STG_B (4*ARR_B)
#define SMEM_GEMM (2*STG_B)

#define GEMM_MAINLOOP(A_PTR, W_PTR, ACC) \
    const float* Ab = (A_PTR) + (size_t)m0 * Dn; \
    const float* Wb = (W_PTR) + (size_t)n0 * Dn; \
    auto prefetch = [&](int kc, float4* pa, float4* pw) { \
        _Pragma("unroll") \
        for (int t = 0; t < 4; t++) { \
            int id = tid + t * 256; \
            int row = id >> 3, c4 = id & 7; \
            pa[t] = *reinterpret_cast<const float4*>(Ab + (size_t)row * Dn + kc * BK + c4 * 4); \
            pw[t] = *reinterpret_cast<const float4*>(Wb + (size_t)row * Dn + kc * BK + c4 * 4); \
        } \
    }; \
    auto stage_store = [&](int st, const float4* pa, const float4* pw) { \
        char* s = smg + st * STG_B; \
        _Pragma("unroll") \
        for (int t = 0; t < 4; t++) { \
            int id = tid + t * 256; \
            int row = id >> 3, c4 = id & 7; \
            size_t off = ((size_t)row * SAstr + c4 * 4) * 2; \
            float r0, r1, r2, r3; \
            uint32_t h01 = packbf_hi(pa[t].x, pa[t].y, r0, r1); \
            uint32_t h23 = packbf_hi(pa[t].z, pa[t].w, r2, r3); \
            *reinterpret_cast<uint2*>(s + off)             = make_uint2(h01, h23); \
            *reinterpret_cast<uint2*>(s + ARR_B + off)     = make_uint2(packbf(r0, r1), packbf(r2, r3)); \
            uint32_t w01 = packbf_hi(pw[t].x, pw[t].y, r0, r1); \
            uint32_t w23 = packbf_hi(pw[t].z, pw[t].w, r2, r3); \
            *reinterpret_cast<uint2*>(s + 2 * ARR_B + off) = make_uint2(w01, w23); \
            *reinterpret_cast<uint2*>(s + 3 * ARR_B + off) = make_uint2(packbf(r0, r1), packbf(r2, r3)); \
        } \
    }; \
    { float4 pa[4], pw[4]; prefetch(0, pa, pw); stage_store(0, pa, pw); } \
    __syncthreads(); \
    _Pragma("unroll 1") \
    for (int kc = 0; kc < Dn / BK; kc++) { \
        float4 pa[4], pw[4]; \
        if (kc + 1 < Dn / BK) prefetch(kc + 1, pa, pw); \
        const char* s = smg + (kc & 1) * STG_B; \
        _Pragma("unroll") \
        for (int ks = 0; ks < 2; ks++) { \
            const int k0 = ks * 16; \
            uint32_t ah[2][4], al[2][4]; \
            _Pragma("unroll") \
            for (int t = 0; t < 2; t++) { \
                int r = wm + t * 16 + g; \
                size_t o0 = ((size_t)r * SAstr + k0 + tg * 2) * 2; \
                size_t o1 = ((size_t)(r + 8) * SAstr + k0 + tg * 2) * 2; \
                ah[t][0] = *reinterpret_cast<const uint32_t*>(s + o0); \
                ah[t][1] = *reinterpret_cast<const uint32_t*>(s + o1); \
                ah[t][2] = *reinterpret_cast<const uint32_t*>(s + o0 + 16); \
                ah[t][3] = *reinterpret_cast<const uint32_t*>(s + o1 + 16); \
                al[t][0] = *reinterpret_cast<const uint32_t*>(s + ARR_B + o0); \
                al[t][1] = *reinterpret_cast<const uint32_t*>(s + ARR_B + o1); \
                al[t][2] = *reinterpret_cast<const uint32_t*>(s + ARR_B + o0 + 16); \
                al[t][3] = *reinterpret_cast<const uint32_t*>(s + ARR_B + o1 + 16); \
            } \
            uint32_t bh[8][2], bl[8][2]; \
            _Pragma("unroll") \
            for (int j = 0; j < 8; j++) { \
                int r = wn + j * 8 + g; \
                size_t o = ((size_t)r * SAstr + k0 + tg * 2) * 2; \
                bh[j][0] = *reinterpret_cast<const uint32_t*>(s + 2 * ARR_B + o); \
                bh[j][1] = *reinterpret_cast<const uint32_t*>(s + 2 * ARR_B + o + 16); \
                bl[j][0] = *reinterpret_cast<const uint32_t*>(s + 3 * ARR_B + o); \
                bl[j][1] = *reinterpret_cast<const uint32_t*>(s + 3 * ARR_B + o + 16); \
            } \
            _Pragma("unroll") \
            for (int t = 0; t < 2; t++) \
                _Pragma("unroll") \
                for (int j = 0; j < 8; j++) { \
                    mma_bf16(ACC[t][j], ah[t], bh[j]); \
                    mma_bf16(ACC[t][j], ah[t], bl[j]); \
                    mma_bf16(ACC[t][j], al[t], bh[j]); \
                } \
        } \
        if (kc + 1 < Dn / BK) stage_store((kc + 1) & 1, pa, pw); \
        __syncthreads(); \
    }

// ---------------------------------------------------------------------------
// QKV projection GEMM: z=0 -> Q (scaled 1/8, bf16 hi/lo), z=1 -> K (bf16 hi/lo),
// z=2 -> V transposed per-head (bf16 hi/lo)
// ---------------------------------------------------------------------------
__global__ __launch_bounds__(256) void gemm_qkv(
    const float* __restrict__ A,
    const float* __restrict__ W0, const float* __restrict__ W1, const float* __restrict__ W2)
{
    extern __shared__ __align__(16) char smg[];
    const int tid  = threadIdx.x;
    const int lane = tid & 31;
    const int g    = lane >> 2;
    const int tg   = lane & 3;
    const int wid  = tid >> 5;
    const int n0 = blockIdx.x * 128, m0 = blockIdx.y * 128;
    const int z  = blockIdx.z;
    const float* W = (z == 0) ? W0 : (z == 1 ? W1 : W2);
    const int wm = (wid & 3) * 32;
    const int wn = (wid >> 2) * 64;

    float acc[2][8][4];
    #pragma unroll
    for (int t = 0; t < 2; t++)
        #pragma unroll
        for (int j = 0; j < 8; j++)
            #pragma unroll
            for (int e = 0; e < 4; e++) acc[t][j][e] = 0.0f;

    GEMM_MAINLOOP(A, W, acc)

    // Epilogue
    if (z < 2) {
        __nv_bfloat16* Oh = (z == 0) ? g_qh : g_kh;
        __nv_bfloat16* Ol = (z == 0) ? g_ql : g_kl;
        const float sc = (z == 0) ? 0.125f : 1.0f;
        #pragma unroll
        for (int t = 0; t < 2; t++)
            #pragma unroll
            for (int j = 0; j < 8; j++) {
                int r = m0 + wm + t * 16 + g;
                int c = n0 + wn + j * 8 + tg * 2;
                float v0 = acc[t][j][0] * sc, v1 = acc[t][j][1] * sc;
                float v2 = acc[t][j][2] * sc, v3 = acc[t][j][3] * sc;
                float r0, r1;
                uint32_t h = packbf_hi(v0, v1, r0, r1);
                *reinterpret_cast<uint32_t*>(&Oh[(size_t)r * Dn + c]) = h;
                *reinterpret_cast<uint32_t*>(&Ol[(size_t)r * Dn + c]) = packbf(r0, r1);
                h = packbf_hi(v2, v3, r0, r1);
                *reinterpret_cast<uint32_t*>(&Oh[(size_t)(r + 8) * Dn + c]) = h;
                *reinterpret_cast<uint32_t*>(&Ol[(size_t)(r + 8) * Dn + c]) = packbf(r0, r1);
            }
    } else {
        #pragma unroll
        for (int t = 0; t < 2; t++)
            #pragma unroll
            for (int j = 0; j < 8; j++) {
                int r = m0 + wm + t * 16 + g;
                int c = n0 + wn + j * 8 + tg * 2;
                #pragma unroll
                for (int e = 0; e < 4; e++) {
                    int rr = r + (e >> 1) * 8;
                    int cc = c + (e & 1);
                    float v = acc[t][j][e];
                    __nv_bfloat16 hv = __float2bfloat16(v);
                    size_t ad = ((size_t)(((rr >> 11) * Hn + (cc >> 6)) * HDn + (cc & 63))) * Nn
                              + (rr & (Nn - 1));
                    g_vth[ad] = hv;
                    g_vtl[ad] = __float2bfloat16(v - __bfloat162float(hv));
                }
            }
    }
}

// ---------------------------------------------------------------------------
// Output projection GEMM (fp32 in/out), unchanged bf16x3 path
// ---------------------------------------------------------------------------
__global__ __launch_bounds__(256) void gemm_out(
    const float* __restrict__ A, const float* __restrict__ W, float* __restrict__ C)
{
    extern __shared__ __align__(16) char smg[];
    const int tid  = threadIdx.x;
    const int lane = tid & 31;
    const int g    = lane >> 2;
    const int tg   = lane & 3;
    const int wid  = tid >> 5;
    const int n0 = blockIdx.x * 128, m0 = blockIdx.y * 128;
    const int wm = (wid & 3) * 32;
    const int wn = (wid >> 2) * 64;

    float acc[2][8][4];
    #pragma unroll
    for (int t = 0; t < 2; t++)
        #pragma unroll
        for (int j = 0; j < 8; j++)
            #pragma unroll
            for (int e = 0; e < 4; e++) acc[t][j][e] = 0.0f;

    GEMM_MAINLOOP(A, W, acc)

    #pragma unroll
    for (int t = 0; t < 2; t++)
        #pragma unroll
        for (int j = 0; j < 8; j++) {
            int row = m0 + wm + t * 16 + g;
            int col = n0 + wn + j * 8 + tg * 2;
            *reinterpret_cast<float2*>(C + (size_t)row * Dn + col) =
                make_float2(acc[t][j][0], acc[t][j][1]);
            *reinterpret_cast<float2*>(C + (size_t)(row + 8) * Dn + col) =
                make_float2(acc[t][j][2], acc[t][j][3]);
        }
}

// ===========================================================================
// Tensor-core flash attention: 128 q-rows per CTA (8 warps x 16 rows),
// k-tiles of 128 keys, bf16x3 for S=QK^T and O+=PV, cp.async double buffer,
// ldmatrix B-operand loads, softmax on register fragments.
// ===========================================================================
#define KSTR 144                      // bytes per K-tile row (64 bf16 + pad)
#define VSTR 272                      // bytes per VT-tile row (128 bf16 + pad)
#define KTILE_B (128*KSTR)            // 18432
#define VTILE_B (64*VSTR)             // 17408
#define MOFF    (2*KTILE_B + 2*VTILE_B)
#define STG_ATT (MOFF + 512)          // 72192
#define SMEM_ATT (2*STG_ATT)          // 144384

__global__ __launch_bounds__(256) void attn_mma(const float* __restrict__ bias) {
    extern __shared__ __align__(16) char sma[];
    const uint32_t sb = smem_u32(sma);
    const int tid  = threadIdx.x;
    const int lane = tid & 31;
    const int w    = tid >> 5;
    const int g    = lane >> 2;
    const int tg   = lane & 3;
    const int q0 = blockIdx.x * 128;
    const int h  = blockIdx.y;
    const int b  = blockIdx.z;

    // ---- Q fragments from gmem (once) ----
    uint32_t qh[4][4], ql[4][4];
    {
        const size_t rbase = (size_t)(b * Nn + q0 + w * 16) * Dn + h * HDn;
        #pragma unroll
        for (int c = 0; c < 4; c++) {
            size_t o0 = rbase + (size_t)g * Dn + c * 16 + tg * 2;
            size_t o1 = rbase + (size_t)(g + 8) * Dn + c * 16 + tg * 2;
            qh[c][0] = *reinterpret_cast<const uint32_t*>(&g_qh[o0]);
            qh[c][1] = *reinterpret_cast<const uint32_t*>(&g_qh[o1]);
            qh[c][2] = *reinterpret_cast<const uint32_t*>(&g_qh[o0 + 8]);
            qh[c][3] = *reinterpret_cast<const uint32_t*>(&g_qh[o1 + 8]);
            ql[c][0] = *reinterpret_cast<const uint32_t*>(&g_ql[o0]);
            ql[c][1] = *reinterpret_cast<const uint32_t*>(&g_ql[o1]);
            ql[c][2] = *reinterpret_cast<const uint32_t*>(&g_ql[o0 + 8]);
            ql[c][3] = *reinterpret_cast<const uint32_t*>(&g_ql[o1 + 8]);
        }
    }

    const char* kh_base = (const char*)g_kh + ((size_t)(b * Nn) * Dn + h * HDn) * 2;
    const char* kl_base = (const char*)g_kl + ((size_t)(b * Nn) * Dn + h * HDn) * 2;
    const char* vh_base = (const char*)g_vth + ((size_t)(b * Hn + h) * HDn) * Nn * 2;
    const char* vl_base = (const char*)g_vtl + ((size_t)(b * Hn + h) * HDn) * Nn * 2;
    const char* mk_base = (const char*)g_maskf + (size_t)(b * Nn) * 4;

    auto prefetch = [&](int kt) {
        const uint32_t u = sb + (kt & 1) * STG_ATT;
        const size_t kof = (size_t)kt * 128 * Dn * 2;   // 128 token rows
        #pragma unroll
        for (int t = 0; t < 4; t++) {
            int id = tid + t * 256;
            int row = id >> 3, c = id & 7;              // K: 128 rows x 8 chunks
            cp16(u + row * KSTR + c * 16,           kh_base + kof + (size_t)row * (Dn * 2) + c * 16);
            cp16(u + KTILE_B + row * KSTR + c * 16, kl_base + kof + (size_t)row * (Dn * 2) + c * 16);
            int vr = id >> 4, vc = id & 15;             // VT: 64 rows x 16 chunks
            cp16(u + 2 * KTILE_B + vr * VSTR + vc * 16,
                 vh_base + (size_t)vr * (Nn * 2) + kt * 256 + vc * 16);
            cp16(u + 2 * KTILE_B + VTILE_B + vr * VSTR + vc * 16,
                 vl_base + (size_t)vr * (Nn * 2) + kt * 256 + vc * 16);
        }
        if (tid < 32) cp16(u + MOFF + tid * 16, mk_base + (size_t)kt * 512 + tid * 16);
        cp_commit();
    };

    float O[8][4];
    #pragma unroll
    for (int j = 0; j < 8; j++)
        #pragma unroll
        for (int e = 0; e < 4; e++) O[j][e] = 0.0f;
    float m0r = -3e38f, m1r = -3e38f, l0 = 0.0f, l1 = 0.0f;

    prefetch(0);

    const float* bb = bias + ((size_t)(b * Nn) + q0 + w * 16) * Nn;

    #pragma unroll 1
    for (int kt = 0; kt < Nn / 128; kt++) {
        cp_wait0();
        __syncthreads();
        const uint32_t u = sb + (kt & 1) * STG_ATT;
        if (kt + 1 < Nn / 128) prefetch(kt + 1);

        // ---- S = Q K^T (bf16x3) ----
        float Sf[16][4];
        #pragma unroll
        for (int j = 0; j < 16; j++)
            #pragma unroll
            for (int e = 0; e < 4; e++) Sf[j][e] = 0.0f;

        #pragma unroll
        for (int c = 0; c < 4; c++) {
            #pragma unroll
            for (int jp = 0; jp < 8; jp++) {
                const int mrow = 8 * (2 * jp + ((lane >> 4) & 1)) + (lane & 7);
                const int mcol = 16 * c + ((lane >> 3) & 1) * 8;
                const uint32_t ad = u + mrow * KSTR + mcol * 2;
                uint32_t bh[4], bl[4];
                ldm_x4(bh, ad);
                ldm_x4(bl, ad + KTILE_B);
                mma_bf16(Sf[2 * jp],     qh[c], &bh[0]);
                mma_bf16(Sf[2 * jp],     qh[c], &bl[0]);
                mma_bf16(Sf[2 * jp],     ql[c], &bh[0]);
                mma_bf16(Sf[2 * jp + 1], qh[c], &bh[2]);
                mma_bf16(Sf[2 * jp + 1], qh[c], &bl[2]);
                mma_bf16(Sf[2 * jp + 1], ql[c], &bh[2]);
            }
        }

        // ---- bias + mask ----
        const float* bt = bb + (size_t)kt * 128;
        #pragma unroll
        for (int j = 0; j < 16; j++) {
            float2 mv = *reinterpret_cast<const float2*>(sma + (kt & 1) * STG_ATT + MOFF
                                                         + (8 * j + 2 * tg) * 4);
            float2 bv0 = *reinterpret_cast<const float2*>(bt + (size_t)g * Nn + 8 * j + 2 * tg);
            float2 bv1 = *reinterpret_cast<const float2*>(bt + (size_t)(g + 8) * Nn + 8 * j + 2 * tg);
            Sf[j][0] += bv0.x + mv.x; Sf[j][1] += bv0.y + mv.y;
            Sf[j][2] += bv1.x + mv.x; Sf[j][3] += bv1.y + mv.y;
        }

        // ---- online softmax on fragments ----
        float mx0 = -3e38f, mx1 = -3e38f;
        #pragma unroll
        for (int j = 0; j < 16; j++) {
            mx0 = fmaxf(mx0, fmaxf(Sf[j][0], Sf[j][1]));
            mx1 = fmaxf(mx1, fmaxf(Sf[j][2], Sf[j][3]));
        }
        #pragma unroll
        for (int off = 1; off < 4; off <<= 1) {
            mx0 = fmaxf(mx0, __shfl_xor_sync(0xffffffffu, mx0, off));
            mx1 = fmaxf(mx1, __shfl_xor_sync(0xffffffffu, mx1, off));
        }
        const float mn0 = fmaxf(m0r, mx0), mn1 = fmaxf(m1r, mx1);
        const float sc0 = __expf(m0r - mn0), sc1 = __expf(m1r - mn1);
        m0r = mn0; m1r = mn1;
        float sum0 = 0.0f, sum1 = 0.0f;
        #pragma unroll
        for (int j = 0; j < 16; j++) {
            Sf[j][0] = __expf(Sf[j][0] - mn0);
            Sf[j][1] = __expf(Sf[j][1] - mn0);
            Sf[j][2] = __expf(Sf[j][2] - mn1);
            Sf[j][3] = __expf(Sf[j][3] - mn1);
            sum0 += Sf[j][0] + Sf[j][1];
            sum1 += Sf[j][2] + Sf[j][3];
        }
        #pragma unroll
        for (int off = 1; off < 4; off <<= 1) {
            sum0 += __shfl_xor_sync(0xffffffffu, sum0, off);
            sum1 += __shfl_xor_sync(0xffffffffu, sum1, off);
        }
        l0 = l0 * sc0 + sum0;
        l1 = l1 * sc1 + sum1;
        #pragma unroll
        for (int j = 0; j < 8; j++) {
            O[j][0] *= sc0; O[j][1] *= sc0;
            O[j][2] *= sc1; O[j][3] *= sc1;
        }

        // ---- O += P V (bf16x3), P fragments built on the fly from Sf ----
        const uint32_t uV = u + 2 * KTILE_B;
        #pragma unroll
        for (int c = 0; c < 8; c++) {
            uint32_t ph[4], pl[4];
            packhl(Sf[2 * c][0],     Sf[2 * c][1],     ph[0], pl[0]);
            packhl(Sf[2 * c][2],     Sf[2 * c][3],     ph[1], pl[1]);
            packhl(Sf[2 * c + 1][0], Sf[2 * c + 1][1], ph[2], pl[2]);
            packhl(Sf[2 * c + 1][2], Sf[2 * c + 1][3], ph[3], pl[3]);
            #pragma unroll
            for (int jp = 0; jp < 4; jp++) {
                const int mrow = 8 * (2 * jp + ((lane >> 4) & 1)) + (lane & 7);
                const int mcol = 16 * c + ((lane >> 3) & 1) * 8;
                const uint32_t ad = uV + mrow * VSTR + mcol * 2;
                uint32_t bh[4], bl[4];
                ldm_x4(bh, ad);
                ldm_x4(bl, ad + VTILE_B);
                mma_bf16(O[2 * jp],     ph, &bh[0]);
                mma_bf16(O[2 * jp],     ph, &bl[0]);
                mma_bf16(O[2 * jp],     pl, &bh[0]);
                mma_bf16(O[2 * jp + 1], ph, &bh[2]);
                mma_bf16(O[2 * jp + 1], ph, &bl[2]);
                mma_bf16(O[2 * jp + 1], pl, &bh[2]);
            }
        }
    }

    // ---- normalize + write ----
    const float inv0 = 1.0f / l0, inv1 = 1.0f / l1;
    const size_t rbase = (size_t)(b * Nn + q0 + w * 16) * Dn + h * HDn;
    #pragma unroll
    for (int j = 0; j < 8; j++) {
        const int col = 8 * j + 2 * tg;
        *reinterpret_cast<float2*>(&g_attn[rbase + (size_t)g * Dn + col]) =
            make_float2(O[j][0] * inv0, O[j][1] * inv0);
        *reinterpret_cast<float2*>(&g_attn[rbase + (size_t)(g + 8) * Dn + col]) =
            make_float2(O[j][2] * inv1, O[j][3] * inv1);
    }
}

// ---------------------------------------------------------------------------
// Launch. Inputs (metadata order): q, mask, attn_bias, Wq, Wk, Wv, Wo
// ---------------------------------------------------------------------------
extern "C" void kernel_launch(void* const* d_in, const int* in_sizes, int n_in,
                              void* d_out, int out_size) {
    const float* q    = (const float*)d_in[0];
    const int*   mask = (const int*)d_in[1];
    const float* bias = (const float*)d_in[2];
    const float* Wq   = (const float*)d_in[3];
    const float* Wk   = (const float*)d_in[4];
    const float* Wv   = (const float*)d_in[5];
    const float* Wo   = (const float*)d_in[6];
    float* out = (float*)d_out;

    float* ga;
    cudaGetSymbolAddress((void**)&ga, g_attn);

    cudaFuncSetAttribute(gemm_qkv, cudaFuncAttributeMaxDynamicSharedMemorySize, SMEM_GEMM);
    cudaFuncSetAttribute(gemm_out, cudaFuncAttributeMaxDynamicSharedMemorySize, SMEM_GEMM);
    cudaFuncSetAttribute(attn_mma, cudaFuncAttributeMaxDynamicSharedMemorySize, SMEM_ATT);

    mask_prep<<<32, 256>>>(mask);

    gemm_qkv<<<dim3(Dn / 128, MT / 128, 3), 256, SMEM_GEMM>>>(q, Wq, Wk, Wv);

    attn_mma<<<dim3(Nn / 128, Hn, Bn), 256, SMEM_ATT>>>(bias);

    gemm_out<<<dim3(Dn / 128, MT / 128, 1), 256, SMEM_GEMM>>>(ga, Wo, out);
}

// round 8
// speedup vs baseline: 2.5698x; 1.1439x over previous
#include <cuda_runtime.h>
#include <cuda_bf16.h>
#include <cstdint>

// Problem constants
#define Bn  4
#define Nn  2048
#define Dn  512
#define Hn  8
#define HDn 64
#define MT  (Bn*Nn)   // 8192 rows

// Scratch (allocation-free rule: __device__ globals)
__device__ __nv_bfloat16 g_qh[MT*Dn], g_ql[MT*Dn];           // Q proj, scaled 1/8, hi/lo
__device__ __nv_bfloat16 g_kh[MT*Dn], g_kl[MT*Dn];           // K proj [tok][dim]
__device__ __nv_bfloat16 g_vth[MT*Dn], g_vtl[MT*Dn];         // V proj transposed [(b,h,d)][tok]
__device__ float g_attn[MT*Dn];
__device__ float g_maskf[Bn*Nn];

// ===========================================================================
// common helpers
// ===========================================================================
__device__ __forceinline__ uint32_t smem_u32(const void* p) {
    uint32_t a;
    asm("{ .reg .u64 t; cvta.to.shared.u64 t, %1; cvt.u32.u64 %0, t; }" : "=r"(a) : "l"(p));
    return a;
}
__device__ __forceinline__ void mma_bf16(float* c, const uint32_t* a, const uint32_t* b) {
    asm volatile("mma.sync.aligned.m16n8k16.row.col.f32.bf16.bf16.f32 "
        "{%0,%1,%2,%3}, {%4,%5,%6,%7}, {%8,%9}, {%0,%1,%2,%3};"
        : "+f"(c[0]), "+f"(c[1]), "+f"(c[2]), "+f"(c[3])
        : "r"(a[0]), "r"(a[1]), "r"(a[2]), "r"(a[3]), "r"(b[0]), "r"(b[1]));
}
__device__ __forceinline__ void ldm_x4(uint32_t* r, uint32_t saddr) {
    asm volatile("ldmatrix.sync.aligned.m8n8.x4.shared.b16 {%0,%1,%2,%3}, [%4];"
        : "=r"(r[0]), "=r"(r[1]), "=r"(r[2]), "=r"(r[3]) : "r"(saddr));
}
__device__ __forceinline__ void cp16(uint32_t saddr, const void* g) {
    asm volatile("cp.async.ca.shared.global [%0], [%1], 16;" :: "r"(saddr), "l"(g));
}
__device__ __forceinline__ void cp_commit() { asm volatile("cp.async.commit_group;" ::: "memory"); }
__device__ __forceinline__ void cp_wait0()  { asm volatile("cp.async.wait_group 0;" ::: "memory"); }

__device__ __forceinline__ uint32_t packbf_hi(float x, float y, float& rx, float& ry) {
    __nv_bfloat16 hx = __float2bfloat16(x), hy = __float2bfloat16(y);
    rx = x - __bfloat162float(hx);
    ry = y - __bfloat162float(hy);
    return (uint32_t)__bfloat16_as_ushort(hx) | ((uint32_t)__bfloat16_as_ushort(hy) << 16);
}
__device__ __forceinline__ uint32_t packbf(float x, float y) {
    return (uint32_t)__bfloat16_as_ushort(__float2bfloat16(x)) |
           ((uint32_t)__bfloat16_as_ushort(__float2bfloat16(y)) << 16);
}
__device__ __forceinline__ void packhl(float x, float y, uint32_t& h, uint32_t& l) {
    float rx, ry;
    h = packbf_hi(x, y, rx, ry);
    l = packbf(rx, ry);
}

// ===========================================================================
// mask -> float addend (0 / -1e30)
// ===========================================================================
__global__ void mask_prep(const int* __restrict__ mask) {
    int i = blockIdx.x * blockDim.x + threadIdx.x;
    if (i < Bn * Nn) g_maskf[i] = mask[i] ? -1e30f : 0.0f;
}

// ===========================================================================
// bf16x3 GEMM mainloop: CTA 256 thr, tile 128x128, BK=32, 2-stage smem,
// ldmatrix fragment loads (80B rows, conflict-free), 2 CTAs/SM.
// ===========================================================================
#define BK    32
#define SAstr 40                    // bf16 elems per smem row (80 B, 16B-aligned)
#define ARR_B (128*SAstr*2)         // 10240 B per array
#define STG_B (4*ARR_B)             // A_hi | A_lo | W_hi | W_lo
#define SMEM_GEMM (2*STG_B)         // 81920 B

#define GEMM_MAINLOOP(A_PTR, W_PTR, ACC) \
    const uint32_t sU = smem_u32(smg); \
    const float* Ab = (A_PTR) + (size_t)m0 * Dn; \
    const float* Wb = (W_PTR) + (size_t)n0 * Dn; \
    auto prefetch = [&](int kc, float4* pa, float4* pw) { \
        _Pragma("unroll") \
        for (int t = 0; t < 4; t++) { \
            int id = tid + t * 256; \
            int row = id >> 3, c4 = id & 7; \
            pa[t] = *reinterpret_cast<const float4*>(Ab + (size_t)row * Dn + kc * BK + c4 * 4); \
            pw[t] = *reinterpret_cast<const float4*>(Wb + (size_t)row * Dn + kc * BK + c4 * 4); \
        } \
    }; \
    auto stage_store = [&](int st, const float4* pa, const float4* pw) { \
        char* s = smg + st * STG_B; \
        _Pragma("unroll") \
        for (int t = 0; t < 4; t++) { \
            int id = tid + t * 256; \
            int row = id >> 3, c4 = id & 7; \
            size_t off = ((size_t)row * SAstr + c4 * 4) * 2; \
            float r0, r1, r2, r3; \
            uint32_t h01 = packbf_hi(pa[t].x, pa[t].y, r0, r1); \
            uint32_t h23 = packbf_hi(pa[t].z, pa[t].w, r2, r3); \
            *reinterpret_cast<uint2*>(s + off)             = make_uint2(h01, h23); \
            *reinterpret_cast<uint2*>(s + ARR_B + off)     = make_uint2(packbf(r0, r1), packbf(r2, r3)); \
            uint32_t w01 = packbf_hi(pw[t].x, pw[t].y, r0, r1); \
            uint32_t w23 = packbf_hi(pw[t].z, pw[t].w, r2, r3); \
            *reinterpret_cast<uint2*>(s + 2 * ARR_B + off) = make_uint2(w01, w23); \
            *reinterpret_cast<uint2*>(s + 3 * ARR_B + off) = make_uint2(packbf(r0, r1), packbf(r2, r3)); \
        } \
    }; \
    { float4 pa[4], pw[4]; prefetch(0, pa, pw); stage_store(0, pa, pw); } \
    __syncthreads(); \
    _Pragma("unroll 1") \
    for (int kc = 0; kc < Dn / BK; kc++) { \
        float4 pa[4], pw[4]; \
        if (kc + 1 < Dn / BK) prefetch(kc + 1, pa, pw); \
        const uint32_t s = sU + (kc & 1) * STG_B; \
        _Pragma("unroll") \
        for (int ks = 0; ks < 2; ks++) { \
            const int k0 = ks * 16; \
            uint32_t ah[2][4], al[2][4]; \
            _Pragma("unroll") \
            for (int t = 0; t < 2; t++) { \
                uint32_t ra = wm + t * 16 + (lane & 15); \
                uint32_t ad = s + (ra * SAstr + k0 + (lane >> 4) * 8) * 2; \
                ldm_x4(ah[t], ad); \
                ldm_x4(al[t], ad + ARR_B); \
            } \
            _Pragma("unroll") \
            for (int jj = 0; jj < 4; jj++) { \
                uint32_t rb = wn + 8 * (2 * jj + ((lane >> 4) & 1)) + (lane & 7); \
                uint32_t ad = s + 2 * ARR_B + (rb * SAstr + k0 + ((lane >> 3) & 1) * 8) * 2; \
                uint32_t bh[4], bl[4]; \
                ldm_x4(bh, ad); \
                ldm_x4(bl, ad + ARR_B); \
                _Pragma("unroll") \
                for (int t = 0; t < 2; t++) { \
                    mma_bf16(ACC[t][2 * jj],     ah[t], &bh[0]); \
                    mma_bf16(ACC[t][2 * jj],     ah[t], &bl[0]); \
                    mma_bf16(ACC[t][2 * jj],     al[t], &bh[0]); \
                    mma_bf16(ACC[t][2 * jj + 1], ah[t], &bh[2]); \
                    mma_bf16(ACC[t][2 * jj + 1], ah[t], &bl[2]); \
                    mma_bf16(ACC[t][2 * jj + 1], al[t], &bh[2]); \
                } \
            } \
        } \
        if (kc + 1 < Dn / BK) stage_store((kc + 1) & 1, pa, pw); \
        __syncthreads(); \
    }

// ---------------------------------------------------------------------------
// QKV projection GEMM: z=0 -> Q (scaled 1/8, bf16 hi/lo), z=1 -> K (bf16 hi/lo),
// z=2 -> V transposed per-head (bf16 hi/lo)
// ---------------------------------------------------------------------------
__global__ __launch_bounds__(256, 2) void gemm_qkv(
    const float* __restrict__ A,
    const float* __restrict__ W0, const float* __restrict__ W1, const float* __restrict__ W2)
{
    extern __shared__ __align__(16) char smg[];
    const int tid  = threadIdx.x;
    const int lane = tid & 31;
    const int g    = lane >> 2;
    const int tg   = lane & 3;
    const int wid  = tid >> 5;
    const int n0 = blockIdx.x * 128, m0 = blockIdx.y * 128;
    const int z  = blockIdx.z;
    const float* W = (z == 0) ? W0 : (z == 1 ? W1 : W2);
    const int wm = (wid & 3) * 32;
    const int wn = (wid >> 2) * 64;

    float acc[2][8][4];
    #pragma unroll
    for (int t = 0; t < 2; t++)
        #pragma unroll
        for (int j = 0; j < 8; j++)
            #pragma unroll
            for (int e = 0; e < 4; e++) acc[t][j][e] = 0.0f;

    GEMM_MAINLOOP(A, W, acc)

    // Epilogue
    if (z < 2) {
        __nv_bfloat16* Oh = (z == 0) ? g_qh : g_kh;
        __nv_bfloat16* Ol = (z == 0) ? g_ql : g_kl;
        const float sc = (z == 0) ? 0.125f : 1.0f;
        #pragma unroll
        for (int t = 0; t < 2; t++)
            #pragma unroll
            for (int j = 0; j < 8; j++) {
                int r = m0 + wm + t * 16 + g;
                int c = n0 + wn + j * 8 + tg * 2;
                float v0 = acc[t][j][0] * sc, v1 = acc[t][j][1] * sc;
                float v2 = acc[t][j][2] * sc, v3 = acc[t][j][3] * sc;
                float r0, r1;
                uint32_t h = packbf_hi(v0, v1, r0, r1);
                *reinterpret_cast<uint32_t*>(&Oh[(size_t)r * Dn + c]) = h;
                *reinterpret_cast<uint32_t*>(&Ol[(size_t)r * Dn + c]) = packbf(r0, r1);
                h = packbf_hi(v2, v3, r0, r1);
                *reinterpret_cast<uint32_t*>(&Oh[(size_t)(r + 8) * Dn + c]) = h;
                *reinterpret_cast<uint32_t*>(&Ol[(size_t)(r + 8) * Dn + c]) = packbf(r0, r1);
            }
    } else {
        #pragma unroll
        for (int t = 0; t < 2; t++)
            #pragma unroll
            for (int j = 0; j < 8; j++) {
                int r = m0 + wm + t * 16 + g;
                int c = n0 + wn + j * 8 + tg * 2;
                #pragma unroll
                for (int e = 0; e < 4; e++) {
                    int rr = r + (e >> 1) * 8;
                    int cc = c + (e & 1);
                    float v = acc[t][j][e];
                    __nv_bfloat16 hv = __float2bfloat16(v);
                    size_t ad = ((size_t)(((rr >> 11) * Hn + (cc >> 6)) * HDn + (cc & 63))) * Nn
                              + (rr & (Nn - 1));
                    g_vth[ad] = hv;
                    g_vtl[ad] = __float2bfloat16(v - __bfloat162float(hv));
                }
            }
    }
}

// ---------------------------------------------------------------------------
// Output projection GEMM (fp32 in/out)
// ---------------------------------------------------------------------------
__global__ __launch_bounds__(256, 2) void gemm_out(
    const float* __restrict__ A, const float* __restrict__ W, float* __restrict__ C)
{
    extern __shared__ __align__(16) char smg[];
    const int tid  = threadIdx.x;
    const int lane = tid & 31;
    const int g    = lane >> 2;
    const int tg   = lane & 3;
    const int wid  = tid >> 5;
    const int n0 = blockIdx.x * 128, m0 = blockIdx.y * 128;
    const int wm = (wid & 3) * 32;
    const int wn = (wid >> 2) * 64;

    float acc[2][8][4];
    #pragma unroll
    for (int t = 0; t < 2; t++)
        #pragma unroll
        for (int j = 0; j < 8; j++)
            #pragma unroll
            for (int e = 0; e < 4; e++) acc[t][j][e] = 0.0f;

    GEMM_MAINLOOP(A, W, acc)

    #pragma unroll
    for (int t = 0; t < 2; t++)
        #pragma unroll
        for (int j = 0; j < 8; j++) {
            int row = m0 + wm + t * 16 + g;
            int col = n0 + wn + j * 8 + tg * 2;
            *reinterpret_cast<float2*>(C + (size_t)row * Dn + col) =
                make_float2(acc[t][j][0], acc[t][j][1]);
            *reinterpret_cast<float2*>(C + (size_t)(row + 8) * Dn + col) =
                make_float2(acc[t][j][2], acc[t][j][3]);
        }
}

// ===========================================================================
// Tensor-core flash attention: 128 q-rows per CTA (8 warps x 16 rows),
// k-tiles of 64 keys, bf16x3 S and PV, cp.async double buffer, 2 CTAs/SM.
// ===========================================================================
#define KSTR 144                      // bytes per K-tile row (64 bf16 + pad)
#define VSTR 144                      // bytes per VT-tile row (64 bf16 + pad)
#define KARR (64*KSTR)                // 9216 per array (hi or lo)
#define VARR (64*VSTR)                // 9216
#define VOFF (2*KARR)                 // 18432
#define MOFF (2*KARR + 2*VARR)        // 36864
#define STG_ATT (MOFF + 256)          // 37120
#define SMEM_ATT (2*STG_ATT)          // 74240

__global__ __launch_bounds__(256, 2) void attn_mma(const float* __restrict__ bias) {
    extern __shared__ __align__(16) char sma[];
    const uint32_t sb = smem_u32(sma);
    const int tid  = threadIdx.x;
    const int lane = tid & 31;
    const int w    = tid >> 5;
    const int g    = lane >> 2;
    const int tg   = lane & 3;
    const int q0 = blockIdx.x * 128;
    const int h  = blockIdx.y;
    const int b  = blockIdx.z;

    // ---- Q fragments from gmem (once) ----
    uint32_t qh[4][4], ql[4][4];
    {
        const size_t rbase = (size_t)(b * Nn + q0 + w * 16) * Dn + h * HDn;
        #pragma unroll
        for (int c = 0; c < 4; c++) {
            size_t o0 = rbase + (size_t)g * Dn + c * 16 + tg * 2;
            size_t o1 = rbase + (size_t)(g + 8) * Dn + c * 16 + tg * 2;
            qh[c][0] = *reinterpret_cast<const uint32_t*>(&g_qh[o0]);
            qh[c][1] = *reinterpret_cast<const uint32_t*>(&g_qh[o1]);
            qh[c][2] = *reinterpret_cast<const uint32_t*>(&g_qh[o0 + 8]);
            qh[c][3] = *reinterpret_cast<const uint32_t*>(&g_qh[o1 + 8]);
            ql[c][0] = *reinterpret_cast<const uint32_t*>(&g_ql[o0]);
            ql[c][1] = *reinterpret_cast<const uint32_t*>(&g_ql[o1]);
            ql[c][2] = *reinterpret_cast<const uint32_t*>(&g_ql[o0 + 8]);
            ql[c][3] = *reinterpret_cast<const uint32_t*>(&g_ql[o1 + 8]);
        }
    }

    const char* kh_base = (const char*)g_kh + ((size_t)(b * Nn) * Dn + h * HDn) * 2;
    const char* kl_base = (const char*)g_kl + ((size_t)(b * Nn) * Dn + h * HDn) * 2;
    const char* vh_base = (const char*)g_vth + ((size_t)(b * Hn + h) * HDn) * Nn * 2;
    const char* vl_base = (const char*)g_vtl + ((size_t)(b * Hn + h) * HDn) * Nn * 2;
    const char* mk_base = (const char*)g_maskf + (size_t)(b * Nn) * 4;

    auto prefetch = [&](int kt) {
        const uint32_t u = sb + (kt & 1) * STG_ATT;
        const size_t kof = (size_t)kt * 64 * (Dn * 2);
        #pragma unroll
        for (int t = 0; t < 2; t++) {
            int id = tid + t * 256;           // 512 chunks: 64 rows x 8
            int row = id >> 3, c = id & 7;
            cp16(u + row * KSTR + c * 16,        kh_base + kof + (size_t)row * (Dn * 2) + c * 16);
            cp16(u + KARR + row * KSTR + c * 16, kl_base + kof + (size_t)row * (Dn * 2) + c * 16);
            cp16(u + VOFF + row * VSTR + c * 16,
                 vh_base + (size_t)row * (Nn * 2) + kt * 128 + c * 16);
            cp16(u + VOFF + VARR + row * VSTR + c * 16,
                 vl_base + (size_t)row * (Nn * 2) + kt * 128 + c * 16);
        }
        if (tid < 16) cp16(u + MOFF + tid * 16, mk_base + (size_t)kt * 256 + tid * 16);
        cp_commit();
    };

    float O[8][4];
    #pragma unroll
    for (int j = 0; j < 8; j++)
        #pragma unroll
        for (int e = 0; e < 4; e++) O[j][e] = 0.0f;
    float m0r = -3e38f, m1r = -3e38f, l0 = 0.0f, l1 = 0.0f;

    prefetch(0);

    const float* bb = bias + ((size_t)(b * Nn) + q0 + w * 16) * Nn;

    #pragma unroll 1
    for (int kt = 0; kt < Nn / 64; kt++) {
        cp_wait0();
        __syncthreads();
        const uint32_t u = sb + (kt & 1) * STG_ATT;
        if (kt + 1 < Nn / 64) prefetch(kt + 1);

        // ---- S = Q K^T (bf16x3) ----
        float Sf[8][4];
        #pragma unroll
        for (int j = 0; j < 8; j++)
            #pragma unroll
            for (int e = 0; e < 4; e++) Sf[j][e] = 0.0f;

        #pragma unroll
        for (int c = 0; c < 4; c++) {
            #pragma unroll
            for (int jp = 0; jp < 4; jp++) {
                const int mrow = 8 * (2 * jp + ((lane >> 4) & 1)) + (lane & 7);
                const int mcol = 16 * c + ((lane >> 3) & 1) * 8;
                const uint32_t ad = u + mrow * KSTR + mcol * 2;
                uint32_t bh[4], bl[4];
                ldm_x4(bh, ad);
                ldm_x4(bl, ad + KARR);
                mma_bf16(Sf[2 * jp],     qh[c], &bh[0]);
                mma_bf16(Sf[2 * jp],     qh[c], &bl[0]);
                mma_bf16(Sf[2 * jp],     ql[c], &bh[0]);
                mma_bf16(Sf[2 * jp + 1], qh[c], &bh[2]);
                mma_bf16(Sf[2 * jp + 1], qh[c], &bl[2]);
                mma_bf16(Sf[2 * jp + 1], ql[c], &bh[2]);
            }
        }

        // ---- bias + mask ----
        const float* bt = bb + (size_t)kt * 64;
        #pragma unroll
        for (int j = 0; j < 8; j++) {
            float2 mv = *reinterpret_cast<const float2*>(sma + (kt & 1) * STG_ATT + MOFF
                                                         + (8 * j + 2 * tg) * 4);
            float2 bv0 = *reinterpret_cast<const float2*>(bt + (size_t)g * Nn + 8 * j + 2 * tg);
            float2 bv1 = *reinterpret_cast<const float2*>(bt + (size_t)(g + 8) * Nn + 8 * j + 2 * tg);
            Sf[j][0] += bv0.x + mv.x; Sf[j][1] += bv0.y + mv.y;
            Sf[j][2] += bv1.x + mv.x; Sf[j][3] += bv1.y + mv.y;
        }

        // ---- online softmax on fragments ----
        float mx0 = -3e38f, mx1 = -3e38f;
        #pragma unroll
        for (int j = 0; j < 8; j++) {
            mx0 = fmaxf(mx0, fmaxf(Sf[j][0], Sf[j][1]));
            mx1 = fmaxf(mx1, fmaxf(Sf[j][2], Sf[j][3]));
        }
        #pragma unroll
        for (int off = 1; off < 4; off <<= 1) {
            mx0 = fmaxf(mx0, __shfl_xor_sync(0xffffffffu, mx0, off));
            mx1 = fmaxf(mx1, __shfl_xor_sync(0xffffffffu, mx1, off));
        }
        const float mn0 = fmaxf(m0r, mx0), mn1 = fmaxf(m1r, mx1);
        const float sc0 = __expf(m0r - mn0), sc1 = __expf(m1r - mn1);
        m0r = mn0; m1r = mn1;
        float sum0 = 0.0f, sum1 = 0.0f;
        #pragma unroll
        for (int j = 0; j < 8; j++) {
            Sf[j][0] = __expf(Sf[j][0] - mn0);
            Sf[j][1] = __expf(Sf[j][1] - mn0);
            Sf[j][2] = __expf(Sf[j][2] - mn1);
            Sf[j][3] = __expf(Sf[j][3] - mn1);
            sum0 += Sf[j][0] + Sf[j][1];
            sum1 += Sf[j][2] + Sf[j][3];
        }
        #pragma unroll
        for (int off = 1; off < 4; off <<= 1) {
            sum0 += __shfl_xor_sync(0xffffffffu, sum0, off);
            sum1 += __shfl_xor_sync(0xffffffffu, sum1, off);
        }
        l0 = l0 * sc0 + sum0;
        l1 = l1 * sc1 + sum1;
        #pragma unroll
        for (int j = 0; j < 8; j++) {
            O[j][0] *= sc0; O[j][1] *= sc0;
            O[j][2] *= sc1; O[j][3] *= sc1;
        }

        // ---- O += P V (bf16x3), P fragments built on the fly from Sf ----
        const uint32_t uV = u + VOFF;
        #pragma unroll
        for (int c = 0; c < 4; c++) {
            uint32_t ph[4], pl[4];
            packhl(Sf[2 * c][0],     Sf[2 * c][1],     ph[0], pl[0]);
            packhl(Sf[2 * c][2],     Sf[2 * c][3],     ph[1], pl[1]);
            packhl(Sf[2 * c + 1][0], Sf[2 * c + 1][1], ph[2], pl[2]);
            packhl(Sf[2 * c + 1][2], Sf[2 * c + 1][3], ph[3], pl[3]);
            #pragma unroll
            for (int jp = 0; jp < 4; jp++) {
                const int mrow = 8 * (2 * jp + ((lane >> 4) & 1)) + (lane & 7);
                const int mcol = 16 * c + ((lane >> 3) & 1) * 8;
                const uint32_t ad = uV + mrow * VSTR + mcol * 2;
                uint32_t vh[4], vl[4];
                ldm_x4(vh, ad);
                ldm_x4(vl, ad + VARR);
                mma_bf16(O[2 * jp],     ph, &vh[0]);
                mma_bf16(O[2 * jp],     ph, &vl[0]);
                mma_bf16(O[2 * jp],     pl, &vh[0]);
                mma_bf16(O[2 * jp + 1], ph, &vh[2]);
                mma_bf16(O[2 * jp + 1], ph, &vl[2]);
                mma_bf16(O[2 * jp + 1], pl, &vh[2]);
            }
        }
    }

    // ---- normalize + write ----
    const float inv0 = 1.0f / l0, inv1 = 1.0f / l1;
    const size_t rbase = (size_t)(b * Nn + q0 + w * 16) * Dn + h * HDn;
    #pragma unroll
    for (int j = 0; j < 8; j++) {
        const int col = 8 * j + 2 * tg;
        *reinterpret_cast<float2*>(&g_attn[rbase + (size_t)g * Dn + col]) =
            make_float2(O[j][0] * inv0, O[j][1] * inv0);
        *reinterpret_cast<float2*>(&g_attn[rbase + (size_t)(g + 8) * Dn + col]) =
            make_float2(O[j][2] * inv1, O[j][3] * inv1);
    }
}

// ---------------------------------------------------------------------------
// Launch. Inputs (metadata order): q, mask, attn_bias, Wq, Wk, Wv, Wo
// ---------------------------------------------------------------------------
extern "C" void kernel_launch(void* const* d_in, const int* in_sizes, int n_in,
                              void* d_out, int out_size) {
    const float* q    = (const float*)d_in[0];
    const int*   mask = (const int*)d_in[1];
    const float* bias = (const float*)d_in[2];
    const float* Wq   = (const float*)d_in[3];
    const float* Wk   = (const float*)d_in[4];
    const float* Wv   = (const float*)d_in[5];
    const float* Wo   = (const float*)d_in[6];
    float* out = (float*)d_out;

    float* ga;
    cudaGetSymbolAddress((void**)&ga, g_attn);

    cudaFuncSetAttribute(gemm_qkv, cudaFuncAttributeMaxDynamicSharedMemorySize, SMEM_GEMM);
    cudaFuncSetAttribute(gemm_out, cudaFuncAttributeMaxDynamicSharedMemorySize, SMEM_GEMM);
    cudaFuncSetAttribute(attn_mma, cudaFuncAttributeMaxDynamicSharedMemorySize, SMEM_ATT);

    mask_prep<<<32, 256>>>(mask);

    gemm_qkv<<<dim3(Dn / 128, MT / 128, 3), 256, SMEM_GEMM>>>(q, Wq, Wk, Wv);

    attn_mma<<<dim3(Nn / 128, Hn, Bn), 256, SMEM_ATT>>>(bias);

    gemm_out<<<dim3(Dn / 128, MT / 128, 1), 256, SMEM_GEMM>>>(ga, Wo, out);
}

// round 9
// speedup vs baseline: 2.9714x; 1.1563x over previous
#include <cuda_runtime.h>
#include <cuda_bf16.h>
#include <cstdint>

// Problem constants
#define Bn  4
#define Nn  2048
#define Dn  512
#define Hn  8
#define HDn 64
#define MT  (Bn*Nn)   // 8192 rows

// Scratch (allocation-free rule: __device__ globals)
__device__ __nv_bfloat16 g_xh[MT*Dn], g_xl[MT*Dn];           // input q split
__device__ __nv_bfloat16 g_wh[4*Dn*Dn], g_wl[4*Dn*Dn];       // Wq,Wk,Wv,Wo split
__device__ __nv_bfloat16 g_qh[MT*Dn], g_ql[MT*Dn];           // Q proj (scaled 1/8)
__device__ __nv_bfloat16 g_kh[MT*Dn], g_kl[MT*Dn];           // K proj [tok][dim]
__device__ __nv_bfloat16 g_vth[MT*Dn], g_vtl[MT*Dn];         // V proj transposed [(b,h,d)][tok]
__device__ __nv_bfloat16 g_oh[MT*Dn], g_ol[MT*Dn];           // attention output split
__device__ float g_maskf[Bn*Nn];

// ===========================================================================
// common helpers
// ===========================================================================
__device__ __forceinline__ uint32_t smem_u32(const void* p) {
    uint32_t a;
    asm("{ .reg .u64 t; cvta.to.shared.u64 t, %1; cvt.u32.u64 %0, t; }" : "=r"(a) : "l"(p));
    return a;
}
__device__ __forceinline__ void mma_bf16(float* c, const uint32_t* a, const uint32_t* b) {
    asm volatile("mma.sync.aligned.m16n8k16.row.col.f32.bf16.bf16.f32 "
        "{%0,%1,%2,%3}, {%4,%5,%6,%7}, {%8,%9}, {%0,%1,%2,%3};"
        : "+f"(c[0]), "+f"(c[1]), "+f"(c[2]), "+f"(c[3])
        : "r"(a[0]), "r"(a[1]), "r"(a[2]), "r"(a[3]), "r"(b[0]), "r"(b[1]));
}
__device__ __forceinline__ void ldm_x4(uint32_t* r, uint32_t saddr) {
    asm volatile("ldmatrix.sync.aligned.m8n8.x4.shared.b16 {%0,%1,%2,%3}, [%4];"
        : "=r"(r[0]), "=r"(r[1]), "=r"(r[2]), "=r"(r[3]) : "r"(saddr));
}
__device__ __forceinline__ void cp16(uint32_t saddr, const void* g) {
    asm volatile("cp.async.ca.shared.global [%0], [%1], 16;" :: "r"(saddr), "l"(g));
}
__device__ __forceinline__ void cp_commit() { asm volatile("cp.async.commit_group;" ::: "memory"); }
__device__ __forceinline__ void cp_wait0()  { asm volatile("cp.async.wait_group 0;" ::: "memory"); }
__device__ __forceinline__ void cp_wait1()  { asm volatile("cp.async.wait_group 1;" ::: "memory"); }

__device__ __forceinline__ uint32_t packbf_hi(float x, float y, float& rx, float& ry) {
    __nv_bfloat16 hx = __float2bfloat16(x), hy = __float2bfloat16(y);
    rx = x - __bfloat162float(hx);
    ry = y - __bfloat162float(hy);
    return (uint32_t)__bfloat16_as_ushort(hx) | ((uint32_t)__bfloat16_as_ushort(hy) << 16);
}
__device__ __forceinline__ uint32_t packbf(float x, float y) {
    return (uint32_t)__bfloat16_as_ushort(__float2bfloat16(x)) |
           ((uint32_t)__bfloat16_as_ushort(__float2bfloat16(y)) << 16);
}
__device__ __forceinline__ void packhl(float x, float y, uint32_t& h, uint32_t& l) {
    float rx, ry;
    h = packbf_hi(x, y, rx, ry);
    l = packbf(rx, ry);
}

// ===========================================================================
// prep: mask -> float addend; fp32 -> bf16 hi/lo split
// ===========================================================================
__global__ void mask_prep(const int* __restrict__ mask) {
    int i = blockIdx.x * blockDim.x + threadIdx.x;
    if (i < Bn * Nn) g_maskf[i] = mask[i] ? -1e30f : 0.0f;
}

__global__ void prep_split_x(const float4* __restrict__ src) {
    int i = blockIdx.x * blockDim.x + threadIdx.x;      // over MT*Dn/4
    float4 v = src[i];
    float r0, r1, r2, r3;
    uint32_t h0 = packbf_hi(v.x, v.y, r0, r1);
    uint32_t h1 = packbf_hi(v.z, v.w, r2, r3);
    reinterpret_cast<uint2*>(g_xh)[i] = make_uint2(h0, h1);
    reinterpret_cast<uint2*>(g_xl)[i] = make_uint2(packbf(r0, r1), packbf(r2, r3));
}

__global__ void prep_split_w(const float4* __restrict__ w0, const float4* __restrict__ w1,
                             const float4* __restrict__ w2, const float4* __restrict__ w3) {
    int i = blockIdx.x * blockDim.x + threadIdx.x;      // over Dn*Dn/4
    int z = blockIdx.y;
    const float4* src = (z == 0) ? w0 : (z == 1) ? w1 : (z == 2) ? w2 : w3;
    float4 v = src[i];
    float r0, r1, r2, r3;
    uint32_t h0 = packbf_hi(v.x, v.y, r0, r1);
    uint32_t h1 = packbf_hi(v.z, v.w, r2, r3);
    size_t o = (size_t)z * (Dn * Dn / 4) + i;
    reinterpret_cast<uint2*>(g_wh)[o] = make_uint2(h0, h1);
    reinterpret_cast<uint2*>(g_wl)[o] = make_uint2(packbf(r0, r1), packbf(r2, r3));
}

// ===========================================================================
// bf16x3 GEMM mainloop on PRE-SPLIT inputs: CTA 256 thr, tile 128x128, BK=32,
// 2-stage cp.async double buffer, ldmatrix fragment loads, 2 CTAs/SM.
// smem per stage: Ah|Al|Bh|Bl, 128 rows x 80B (40 bf16, conflict-free).
// ===========================================================================
#define BK    32
#define SAstr 40
#define ARR_B (128*SAstr*2)         // 10240 B per array
#define STG_B (4*ARR_B)             // 40960 B per stage
#define SMEM_GEMM (2*STG_B)         // 81920 B
#define NCH   (Dn/BK)               // 16

#define GEMM_MAINLOOP(AH, AL, BH, BL, ACC) \
    const uint32_t sU = smem_u32(smg); \
    const __nv_bfloat16* Ah_g = (AH) + (size_t)m0 * Dn; \
    const __nv_bfloat16* Al_g = (AL) + (size_t)m0 * Dn; \
    const __nv_bfloat16* Bh_g = (BH) + (size_t)n0 * Dn; \
    const __nv_bfloat16* Bl_g = (BL) + (size_t)n0 * Dn; \
    auto prefetch = [&](int kc) { \
        const uint32_t u = sU + (kc & 1) * STG_B; \
        _Pragma("unroll") \
        for (int t = 0; t < 2; t++) { \
            int id = tid + t * 256;                   /* 512 = 128 rows x 4 chunks */ \
            int row = id >> 2, c = id & 3; \
            size_t go = (size_t)row * Dn + kc * BK + c * 8;   /* elements */ \
            uint32_t so = u + row * (SAstr * 2) + c * 16; \
            cp16(so,             Ah_g + go); \
            cp16(so + ARR_B,     Al_g + go); \
            cp16(so + 2 * ARR_B, Bh_g + go); \
            cp16(so + 3 * ARR_B, Bl_g + go); \
        } \
        cp_commit(); \
    }; \
    prefetch(0); \
    _Pragma("unroll 1") \
    for (int kc = 0; kc < NCH; kc++) { \
        if (kc + 1 < NCH) { prefetch(kc + 1); cp_wait1(); } else { cp_wait0(); } \
        __syncthreads(); \
        const uint32_t s = sU + (kc & 1) * STG_B; \
        _Pragma("unroll") \
        for (int ks = 0; ks < 2; ks++) { \
            const int k0 = ks * 16; \
            uint32_t ah[2][4], al[2][4]; \
            _Pragma("unroll") \
            for (int t = 0; t < 2; t++) { \
                uint32_t ra = wm + t * 16 + (lane & 15); \
                uint32_t ad = s + (ra * SAstr + k0 + (lane >> 4) * 8) * 2; \
                ldm_x4(ah[t], ad); \
                ldm_x4(al[t], ad + ARR_B); \
            } \
            _Pragma("unroll") \
            for (int jj = 0; jj < 4; jj++) { \
                uint32_t rb = wn + 8 * (2 * jj + ((lane >> 4) & 1)) + (lane & 7); \
                uint32_t ad = s + 2 * ARR_B + (rb * SAstr + k0 + ((lane >> 3) & 1) * 8) * 2; \
                uint32_t bh[4], bl[4]; \
                ldm_x4(bh, ad); \
                ldm_x4(bl, ad + ARR_B); \
                _Pragma("unroll") \
                for (int t = 0; t < 2; t++) { \
                    mma_bf16(ACC[t][2 * jj],     ah[t], &bh[0]); \
                    mma_bf16(ACC[t][2 * jj],     ah[t], &bl[0]); \
                    mma_bf16(ACC[t][2 * jj],     al[t], &bh[0]); \
                    mma_bf16(ACC[t][2 * jj + 1], ah[t], &bh[2]); \
                    mma_bf16(ACC[t][2 * jj + 1], ah[t], &bl[2]); \
                    mma_bf16(ACC[t][2 * jj + 1], al[t], &bh[2]); \
                } \
            } \
        } \
        __syncthreads(); \
    }

// ---------------------------------------------------------------------------
// QKV projection GEMM: z=0 Q (scaled 1/8), z=1 K, z=2 V (smem-transposed)
// ---------------------------------------------------------------------------
#define TSTR 136     // V-transpose smem: tokens per d-row (272 B, 16B-mult)
#define TARR (128*TSTR*2)   // 34816 B

__global__ __launch_bounds__(256, 2) void gemm_qkv() {
    extern __shared__ __align__(16) char smg[];
    const int tid  = threadIdx.x;
    const int lane = tid & 31;
    const int g    = lane >> 2;
    const int tg   = lane & 3;
    const int wid  = tid >> 5;
    const int n0 = blockIdx.x * 128, m0 = blockIdx.y * 128;
    const int z  = blockIdx.z;
    const int wm = (wid & 3) * 32;
    const int wn = (wid >> 2) * 64;

    float acc[2][8][4];
    #pragma unroll
    for (int t = 0; t < 2; t++)
        #pragma unroll
        for (int j = 0; j < 8; j++)
            #pragma unroll
            for (int e = 0; e < 4; e++) acc[t][j][e] = 0.0f;

    const __nv_bfloat16* Wh = g_wh + (size_t)z * Dn * Dn;
    const __nv_bfloat16* Wl = g_wl + (size_t)z * Dn * Dn;
    GEMM_MAINLOOP(g_xh, g_xl, Wh, Wl, acc)

    if (z < 2) {
        __nv_bfloat16* Oh = (z == 0) ? g_qh : g_kh;
        __nv_bfloat16* Ol = (z == 0) ? g_ql : g_kl;
        const float sc = (z == 0) ? 0.125f : 1.0f;
        #pragma unroll
        for (int t = 0; t < 2; t++)
            #pragma unroll
            for (int j = 0; j < 8; j++) {
                int r = m0 + wm + t * 16 + g;
                int c = n0 + wn + j * 8 + tg * 2;
                float v0 = acc[t][j][0] * sc, v1 = acc[t][j][1] * sc;
                float v2 = acc[t][j][2] * sc, v3 = acc[t][j][3] * sc;
                uint32_t h, l;
                packhl(v0, v1, h, l);
                *reinterpret_cast<uint32_t*>(&Oh[(size_t)r * Dn + c]) = h;
                *reinterpret_cast<uint32_t*>(&Ol[(size_t)r * Dn + c]) = l;
                packhl(v2, v3, h, l);
                *reinterpret_cast<uint32_t*>(&Oh[(size_t)(r + 8) * Dn + c]) = h;
                *reinterpret_cast<uint32_t*>(&Ol[(size_t)(r + 8) * Dn + c]) = l;
            }
    } else {
        // V: transpose through smem, then coalesced writes to g_vt[h|l]
        // smem layout: hi at [0, TARR), lo at [TARR, 2*TARR): [dim 128][tok TSTR] bf16
        #pragma unroll
        for (int t = 0; t < 2; t++)
            #pragma unroll
            for (int j = 0; j < 8; j++)
                #pragma unroll
                for (int e = 0; e < 4; e++) {
                    int lr = wm + t * 16 + g + (e >> 1) * 8;        // local token
                    int lc = wn + j * 8 + tg * 2 + (e & 1);         // local dim
                    float v = acc[t][j][e];
                    __nv_bfloat16 hv = __float2bfloat16(v);
                    *reinterpret_cast<__nv_bfloat16*>(smg + (size_t)lc * (TSTR * 2) + lr * 2) = hv;
                    *reinterpret_cast<__nv_bfloat16*>(smg + TARR + (size_t)lc * (TSTR * 2) + lr * 2) =
                        __float2bfloat16(v - __bfloat162float(hv));
                }
        __syncthreads();
        const int dd = tid >> 1;            // 0..127 (local dim)
        const int hf = tid & 1;             // half of 128 tokens
        const int b  = m0 >> 11;
        const int hh = (n0 + dd) >> 6;
        const int d  = (n0 + dd) & 63;
        const size_t dst = (((size_t)(b * Hn + hh)) * HDn + d) * Nn + (m0 & (Nn - 1)) + hf * 64;
        const uint32_t so = (uint32_t)dd * (TSTR * 2) + hf * 128;
        #pragma unroll
        for (int u = 0; u < 8; u++) {
            *reinterpret_cast<uint4*>(&g_vth[dst + u * 8]) =
                *reinterpret_cast<const uint4*>(smg + so + u * 16);
            *reinterpret_cast<uint4*>(&g_vtl[dst + u * 8]) =
                *reinterpret_cast<const uint4*>(smg + TARR + so + u * 16);
        }
    }
}

// ---------------------------------------------------------------------------
// Output projection GEMM: reads pre-split O, writes fp32
// ---------------------------------------------------------------------------
__global__ __launch_bounds__(256, 2) void gemm_out(float* __restrict__ C) {
    extern __shared__ __align__(16) char smg[];
    const int tid  = threadIdx.x;
    const int lane = tid & 31;
    const int g    = lane >> 2;
    const int tg   = lane & 3;
    const int wid  = tid >> 5;
    const int n0 = blockIdx.x * 128, m0 = blockIdx.y * 128;
    const int wm = (wid & 3) * 32;
    const int wn = (wid >> 2) * 64;

    float acc[2][8][4];
    #pragma unroll
    for (int t = 0; t < 2; t++)
        #pragma unroll
        for (int j = 0; j < 8; j++)
            #pragma unroll
            for (int e = 0; e < 4; e++) acc[t][j][e] = 0.0f;

    const __nv_bfloat16* Wh = g_wh + (size_t)3 * Dn * Dn;
    const __nv_bfloat16* Wl = g_wl + (size_t)3 * Dn * Dn;
    GEMM_MAINLOOP(g_oh, g_ol, Wh, Wl, acc)

    #pragma unroll
    for (int t = 0; t < 2; t++)
        #pragma unroll
        for (int j = 0; j < 8; j++) {
            int row = m0 + wm + t * 16 + g;
            int col = n0 + wn + j * 8 + tg * 2;
            *reinterpret_cast<float2*>(C + (size_t)row * Dn + col) =
                make_float2(acc[t][j][0], acc[t][j][1]);
            *reinterpret_cast<float2*>(C + (size_t)(row + 8) * Dn + col) =
                make_float2(acc[t][j][2], acc[t][j][3]);
        }
}

// ===========================================================================
// Tensor-core flash attention: 128 q-rows per CTA (8 warps x 16 rows),
// k-tiles of 64 keys, bf16x3 S and PV, cp.async double buffer, 2 CTAs/SM.
// Grid (h, qtile, b): consecutive CTAs share bias rows -> L2 reuse.
// ===========================================================================
#define KSTR 144
#define VSTR 144
#define KARR (64*KSTR)
#define VARR (64*VSTR)
#define VOFF (2*KARR)
#define MOFF (2*KARR + 2*VARR)
#define STG_ATT (MOFF + 256)
#define SMEM_ATT (2*STG_ATT)

__global__ __launch_bounds__(256, 2) void attn_mma(const float* __restrict__ bias) {
    extern __shared__ __align__(16) char sma[];
    const uint32_t sb = smem_u32(sma);
    const int tid  = threadIdx.x;
    const int lane = tid & 31;
    const int w    = tid >> 5;
    const int g    = lane >> 2;
    const int tg   = lane & 3;
    const int h  = blockIdx.x;
    const int q0 = blockIdx.y * 128;
    const int b  = blockIdx.z;

    // ---- Q fragments from gmem (once) ----
    uint32_t qh[4][4], ql[4][4];
    {
        const size_t rbase = (size_t)(b * Nn + q0 + w * 16) * Dn + h * HDn;
        #pragma unroll
        for (int c = 0; c < 4; c++) {
            size_t o0 = rbase + (size_t)g * Dn + c * 16 + tg * 2;
            size_t o1 = rbase + (size_t)(g + 8) * Dn + c * 16 + tg * 2;
            qh[c][0] = *reinterpret_cast<const uint32_t*>(&g_qh[o0]);
            qh[c][1] = *reinterpret_cast<const uint32_t*>(&g_qh[o1]);
            qh[c][2] = *reinterpret_cast<const uint32_t*>(&g_qh[o0 + 8]);
            qh[c][3] = *reinterpret_cast<const uint32_t*>(&g_qh[o1 + 8]);
            ql[c][0] = *reinterpret_cast<const uint32_t*>(&g_ql[o0]);
            ql[c][1] = *reinterpret_cast<const uint32_t*>(&g_ql[o1]);
            ql[c][2] = *reinterpret_cast<const uint32_t*>(&g_ql[o0 + 8]);
            ql[c][3] = *reinterpret_cast<const uint32_t*>(&g_ql[o1 + 8]);
        }
    }

    const char* kh_base = (const char*)g_kh + ((size_t)(b * Nn) * Dn + h * HDn) * 2;
    const char* kl_base = (const char*)g_kl + ((size_t)(b * Nn) * Dn + h * HDn) * 2;
    const char* vh_base = (const char*)g_vth + ((size_t)(b * Hn + h) * HDn) * Nn * 2;
    const char* vl_base = (const char*)g_vtl + ((size_t)(b * Hn + h) * HDn) * Nn * 2;
    const char* mk_base = (const char*)g_maskf + (size_t)(b * Nn) * 4;

    auto prefetch = [&](int kt) {
        const uint32_t u = sb + (kt & 1) * STG_ATT;
        const size_t kof = (size_t)kt * 64 * (Dn * 2);
        #pragma unroll
        for (int t = 0; t < 2; t++) {
            int id = tid + t * 256;
            int row = id >> 3, c = id & 7;
            cp16(u + row * KSTR + c * 16,        kh_base + kof + (size_t)row * (Dn * 2) + c * 16);
            cp16(u + KARR + row * KSTR + c * 16, kl_base + kof + (size_t)row * (Dn * 2) + c * 16);
            cp16(u + VOFF + row * VSTR + c * 16,
                 vh_base + (size_t)row * (Nn * 2) + kt * 128 + c * 16);
            cp16(u + VOFF + VARR + row * VSTR + c * 16,
                 vl_base + (size_t)row * (Nn * 2) + kt * 128 + c * 16);
        }
        if (tid < 16) cp16(u + MOFF + tid * 16, mk_base + (size_t)kt * 256 + tid * 16);
        cp_commit();
    };

    float O[8][4];
    #pragma unroll
    for (int j = 0; j < 8; j++)
        #pragma unroll
        for (int e = 0; e < 4; e++) O[j][e] = 0.0f;
    float m0r = -3e38f, m1r = -3e38f, l0 = 0.0f, l1 = 0.0f;

    prefetch(0);

    const float* bb = bias + ((size_t)(b * Nn) + q0 + w * 16) * Nn;

    #pragma unroll 1
    for (int kt = 0; kt < Nn / 64; kt++) {
        cp_wait0();
        __syncthreads();
        const uint32_t u = sb + (kt & 1) * STG_ATT;
        if (kt + 1 < Nn / 64) prefetch(kt + 1);

        // ---- S = Q K^T (bf16x3) ----
        float Sf[8][4];
        #pragma unroll
        for (int j = 0; j < 8; j++)
            #pragma unroll
            for (int e = 0; e < 4; e++) Sf[j][e] = 0.0f;

        #pragma unroll
        for (int c = 0; c < 4; c++) {
            #pragma unroll
            for (int jp = 0; jp < 4; jp++) {
                const int mrow = 8 * (2 * jp + ((lane >> 4) & 1)) + (lane & 7);
                const int mcol = 16 * c + ((lane >> 3) & 1) * 8;
                const uint32_t ad = u + mrow * KSTR + mcol * 2;
                uint32_t bh[4], bl[4];
                ldm_x4(bh, ad);
                ldm_x4(bl, ad + KARR);
                mma_bf16(Sf[2 * jp],     qh[c], &bh[0]);
                mma_bf16(Sf[2 * jp],     qh[c], &bl[0]);
                mma_bf16(Sf[2 * jp],     ql[c], &bh[0]);
                mma_bf16(Sf[2 * jp + 1], qh[c], &bh[2]);
                mma_bf16(Sf[2 * jp + 1], qh[c], &bl[2]);
                mma_bf16(Sf[2 * jp + 1], ql[c], &bh[2]);
            }
        }

        // ---- bias + mask ----
        const float* bt = bb + (size_t)kt * 64;
        #pragma unroll
        for (int j = 0; j < 8; j++) {
            float2 mv = *reinterpret_cast<const float2*>(sma + (kt & 1) * STG_ATT + MOFF
                                                         + (8 * j + 2 * tg) * 4);
            float2 bv0 = *reinterpret_cast<const float2*>(bt + (size_t)g * Nn + 8 * j + 2 * tg);
            float2 bv1 = *reinterpret_cast<const float2*>(bt + (size_t)(g + 8) * Nn + 8 * j + 2 * tg);
            Sf[j][0] += bv0.x + mv.x; Sf[j][1] += bv0.y + mv.y;
            Sf[j][2] += bv1.x + mv.x; Sf[j][3] += bv1.y + mv.y;
        }

        // ---- online softmax on fragments ----
        float mx0 = -3e38f, mx1 = -3e38f;
        #pragma unroll
        for (int j = 0; j < 8; j++) {
            mx0 = fmaxf(mx0, fmaxf(Sf[j][0], Sf[j][1]));
            mx1 = fmaxf(mx1, fmaxf(Sf[j][2], Sf[j][3]));
        }
        #pragma unroll
        for (int off = 1; off < 4; off <<= 1) {
            mx0 = fmaxf(mx0, __shfl_xor_sync(0xffffffffu, mx0, off));
            mx1 = fmaxf(mx1, __shfl_xor_sync(0xffffffffu, mx1, off));
        }
        const float mn0 = fmaxf(m0r, mx0), mn1 = fmaxf(m1r, mx1);
        const float sc0 = __expf(m0r - mn0), sc1 = __expf(m1r - mn1);
        m0r = mn0; m1r = mn1;
        float sum0 = 0.0f, sum1 = 0.0f;
        #pragma unroll
        for (int j = 0; j < 8; j++) {
            Sf[j][0] = __expf(Sf[j][0] - mn0);
            Sf[j][1] = __expf(Sf[j][1] - mn0);
            Sf[j][2] = __expf(Sf[j][2] - mn1);
            Sf[j][3] = __expf(Sf[j][3] - mn1);
            sum0 += Sf[j][0] + Sf[j][1];
            sum1 += Sf[j][2] + Sf[j][3];
        }
        #pragma unroll
        for (int off = 1; off < 4; off <<= 1) {
            sum0 += __shfl_xor_sync(0xffffffffu, sum0, off);
            sum1 += __shfl_xor_sync(0xffffffffu, sum1, off);
        }
        l0 = l0 * sc0 + sum0;
        l1 = l1 * sc1 + sum1;
        #pragma unroll
        for (int j = 0; j < 8; j++) {
            O[j][0] *= sc0; O[j][1] *= sc0;
            O[j][2] *= sc1; O[j][3] *= sc1;
        }

        // ---- O += P V (bf16x3) ----
        const uint32_t uV = u + VOFF;
        #pragma unroll
        for (int c = 0; c < 4; c++) {
            uint32_t ph[4], pl[4];
            packhl(Sf[2 * c][0],     Sf[2 * c][1],     ph[0], pl[0]);
            packhl(Sf[2 * c][2],     Sf[2 * c][3],     ph[1], pl[1]);
            packhl(Sf[2 * c + 1][0], Sf[2 * c + 1][1], ph[2], pl[2]);
            packhl(Sf[2 * c + 1][2], Sf[2 * c + 1][3], ph[3], pl[3]);
            #pragma unroll
            for (int jp = 0; jp < 4; jp++) {
                const int mrow = 8 * (2 * jp + ((lane >> 4) & 1)) + (lane & 7);
                const int mcol = 16 * c + ((lane >> 3) & 1) * 8;
                const uint32_t ad = uV + mrow * VSTR + mcol * 2;
                uint32_t vh[4], vl[4];
                ldm_x4(vh, ad);
                ldm_x4(vl, ad + VARR);
                mma_bf16(O[2 * jp],     ph, &vh[0]);
                mma_bf16(O[2 * jp],     ph, &vl[0]);
                mma_bf16(O[2 * jp],     pl, &vh[0]);
                mma_bf16(O[2 * jp + 1], ph, &vh[2]);
                mma_bf16(O[2 * jp + 1], ph, &vl[2]);
                mma_bf16(O[2 * jp + 1], pl, &vh[2]);
            }
        }
    }

    // ---- normalize + write split bf16 ----
    const float inv0 = 1.0f / l0, inv1 = 1.0f / l1;
    const size_t rbase = (size_t)(b * Nn + q0 + w * 16) * Dn + h * HDn;
    #pragma unroll
    for (int j = 0; j < 8; j++) {
        const int col = 8 * j + 2 * tg;
        uint32_t hv, lv;
        packhl(O[j][0] * inv0, O[j][1] * inv0, hv, lv);
        *reinterpret_cast<uint32_t*>(&g_oh[rbase + (size_t)g * Dn + col]) = hv;
        *reinterpret_cast<uint32_t*>(&g_ol[rbase + (size_t)g * Dn + col]) = lv;
        packhl(O[j][2] * inv1, O[j][3] * inv1, hv, lv);
        *reinterpret_cast<uint32_t*>(&g_oh[rbase + (size_t)(g + 8) * Dn + col]) = hv;
        *reinterpret_cast<uint32_t*>(&g_ol[rbase + (size_t)(g + 8) * Dn + col]) = lv;
    }
}

// ---------------------------------------------------------------------------
// Launch. Inputs (metadata order): q, mask, attn_bias, Wq, Wk, Wv, Wo
// ---------------------------------------------------------------------------
extern "C" void kernel_launch(void* const* d_in, const int* in_sizes, int n_in,
                              void* d_out, int out_size) {
    const float* q    = (const float*)d_in[0];
    const int*   mask = (const int*)d_in[1];
    const float* bias = (const float*)d_in[2];
    const float* Wq   = (const float*)d_in[3];
    const float* Wk   = (const float*)d_in[4];
    const float* Wv   = (const float*)d_in[5];
    const float* Wo   = (const float*)d_in[6];
    float* out = (float*)d_out;

    cudaFuncSetAttribute(gemm_qkv, cudaFuncAttributeMaxDynamicSharedMemorySize, SMEM_GEMM);
    cudaFuncSetAttribute(gemm_out, cudaFuncAttributeMaxDynamicSharedMemorySize, SMEM_GEMM);
    cudaFuncSetAttribute(attn_mma, cudaFuncAttributeMaxDynamicSharedMemorySize, SMEM_ATT);

    mask_prep<<<32, 256>>>(mask);
    prep_split_x<<<MT * Dn / 4 / 256, 256>>>((const float4*)q);
    prep_split_w<<<dim3(Dn * Dn / 4 / 256, 4), 256>>>(
        (const float4*)Wq, (const float4*)Wk, (const float4*)Wv, (const float4*)Wo);

    gemm_qkv<<<dim3(Dn / 128, MT / 128, 3), 256, SMEM_GEMM>>>();

    attn_mma<<<dim3(Hn, Nn / 128, Bn), 256, SMEM_ATT>>>(bias);

    gemm_out<<<dim3(Dn / 128, MT / 128, 1), 256, SMEM_GEMM>>>(out);
}